// round 1
// baseline (speedup 1.0000x reference)
#include <cuda_runtime.h>
#include <math.h>

#define BT 16
#define ST 4
#define NB (BT*ST)        // 64 flattened batch
#define CH 512
#define C1 256
#define C2 32
#define L1 1024
#define L1U 2048
#define L2U 4096
#define TOUT 4096

// ---------------- scratch (device globals; no allocation allowed) ----------
__device__ float g_buf1[NB*C1*L1];    // conv1+bn+relu   [64,256,1024]
__device__ float g_buf2[NB*C1*L1U];   // upsample1       [64,256,2048]
__device__ float g_buf3[NB*C2*L1U];   // conv2+bn+relu   [64,32,2048]
__device__ float g_buf4[NB*C2*L2U];   // upsample2       [64,32,4096]
__device__ float g_buf5[NB*3*TOUT];   // conv_out        [64,3,4096]
__device__ double g_loss_acc;
__device__ int    g_valid;

__global__ void init_kernel() { g_loss_acc = 0.0; g_valid = 0; }

// ---------------- fused conv1d(reflect,dilated) + BN(eval) + ReLU ----------
// Output tile: (16*CO_PER) x (16*T_PER) per 256-thread block, 4x4 (or 2x4)
// register block per thread. Weights staged as ws[ci][k][co] so co is
// contiguous; x staged with reflect applied at load.
template<int CI, int CO, int L, int DIL, int CO_PER, int T_PER>
__global__ __launch_bounds__(256) void convbn_kernel(
    const float* __restrict__ x, const float* __restrict__ w,
    const float* __restrict__ gamma, const float* __restrict__ beta,
    const float* __restrict__ mean,  const float* __restrict__ var,
    float* __restrict__ out)
{
    constexpr int CI_STEP = 8;
    constexpr int T_T  = 16 * T_PER;
    constexpr int CO_T = 16 * CO_PER;
    constexpr int XW   = T_T + 2 * DIL;

    __shared__ float xs[CI_STEP][XW];
    __shared__ float ws[CI_STEP][3][CO_T];

    const int b   = blockIdx.z;
    const int t0  = blockIdx.x * T_T;
    const int co0 = blockIdx.y * CO_T;
    const int tid = threadIdx.x;
    const int tx  = tid & 15;        // t group
    const int ty  = tid >> 4;        // co group

    const float* xb = x + (size_t)b * CI * L;

    float acc[CO_PER][T_PER];
#pragma unroll
    for (int i = 0; i < CO_PER; i++)
#pragma unroll
        for (int j = 0; j < T_PER; j++) acc[i][j] = 0.0f;

    for (int ci0 = 0; ci0 < CI; ci0 += CI_STEP) {
        // stage x tile (reflect padding applied here)
        for (int i = tid; i < CI_STEP * XW; i += 256) {
            int r = i / XW, c = i % XW;
            int g = t0 - DIL + c;
            g = (g < 0) ? -g : ((g >= L) ? 2 * L - 2 - g : g);
            xs[r][c] = xb[(size_t)(ci0 + r) * L + g];
        }
        // stage weights as [ci][k][co]
        for (int i = tid; i < CI_STEP * 3 * CO_T; i += 256) {
            int ci = i / (3 * CO_T);
            int r  = i % (3 * CO_T);
            int k  = r / CO_T;
            int co = r % CO_T;
            ws[ci][k][co] = w[((size_t)(co0 + co) * CI + (ci0 + ci)) * 3 + k];
        }
        __syncthreads();

#pragma unroll
        for (int ci = 0; ci < CI_STEP; ci++) {
            float xr[3][T_PER];
#pragma unroll
            for (int k = 0; k < 3; k++)
#pragma unroll
                for (int j = 0; j < T_PER; j++)
                    xr[k][j] = xs[ci][tx * T_PER + k * DIL + j];
            float wr[3][CO_PER];
#pragma unroll
            for (int k = 0; k < 3; k++)
#pragma unroll
                for (int i = 0; i < CO_PER; i++)
                    wr[k][i] = ws[ci][k][ty * CO_PER + i];
#pragma unroll
            for (int i = 0; i < CO_PER; i++)
#pragma unroll
                for (int j = 0; j < T_PER; j++) {
                    float a = acc[i][j];
#pragma unroll
                    for (int k = 0; k < 3; k++)
                        a = fmaf(wr[k][i], xr[k][j], a);
                    acc[i][j] = a;
                }
        }
        __syncthreads();
    }

    // epilogue: BN(eval) + ReLU
#pragma unroll
    for (int i = 0; i < CO_PER; i++) {
        int co = co0 + ty * CO_PER + i;
        float inv = gamma[co] / sqrtf(var[co] + 1e-5f);
        float add = beta[co] - mean[co] * inv;
        float* op = out + ((size_t)b * CO + co) * L + t0 + tx * T_PER;
#pragma unroll
        for (int j = 0; j < T_PER; j++) {
            float v = acc[i][j] * inv + add;
            op[j] = fmaxf(v, 0.0f);
        }
    }
}

// ---------------- linear 2x upsample (align_corners=False) -----------------
__global__ void upsample_kernel(const float* __restrict__ in,
                                float* __restrict__ out, int NC, int Lin)
{
    int idx = blockIdx.x * blockDim.x + threadIdx.x;
    int Lo = 2 * Lin;
    if (idx >= NC * Lo) return;
    int t = idx % Lo;
    int c = idx / Lo;
    const float* p = in + (size_t)c * Lin;
    int m = t >> 1;
    float v;
    if ((t & 1) == 0) {
        v = (m == 0) ? p[0] : fmaf(0.25f, p[m - 1], 0.75f * p[m]);
    } else {
        int m1 = (m + 1 < Lin) ? m + 1 : Lin - 1;
        v = fmaf(0.75f, p[m], 0.25f * p[m1]);
    }
    out[idx] = v;
}

// ---------------- final conv (32->3, dil=32) + bias ------------------------
__global__ __launch_bounds__(256) void conv_out_kernel(
    const float* __restrict__ x, const float* __restrict__ w,
    const float* __restrict__ bias, float* __restrict__ out)
{
    constexpr int CI = C2, L = L2U, DIL = 32, T_T = 256, XW = T_T + 2 * DIL;
    __shared__ float xs[CI][XW];        // 40 KB
    __shared__ float ws[3][CI * 3];
    const int bs = blockIdx.y;
    const int t0 = blockIdx.x * T_T;
    const int tid = threadIdx.x;
    const float* xb = x + (size_t)bs * CI * L;

    for (int i = tid; i < CI * XW; i += 256) {
        int r = i / XW, c = i % XW;
        int g = t0 - DIL + c;
        g = (g < 0) ? -g : ((g >= L) ? 2 * L - 2 - g : g);
        xs[r][c] = xb[(size_t)r * L + g];
    }
    for (int i = tid; i < 3 * CI * 3; i += 256)
        ws[i / (CI * 3)][i % (CI * 3)] = w[i];
    __syncthreads();

    float a0 = bias[0], a1 = bias[1], a2 = bias[2];
    const int t = tid;
#pragma unroll
    for (int ci = 0; ci < CI; ci++) {
        float x0 = xs[ci][t], x1 = xs[ci][t + DIL], x2 = xs[ci][t + 2 * DIL];
        a0 = fmaf(ws[0][ci * 3 + 0], x0, a0); a0 = fmaf(ws[0][ci * 3 + 1], x1, a0); a0 = fmaf(ws[0][ci * 3 + 2], x2, a0);
        a1 = fmaf(ws[1][ci * 3 + 0], x0, a1); a1 = fmaf(ws[1][ci * 3 + 1], x1, a1); a1 = fmaf(ws[1][ci * 3 + 2], x2, a1);
        a2 = fmaf(ws[2][ci * 3 + 0], x0, a2); a2 = fmaf(ws[2][ci * 3 + 1], x1, a2); a2 = fmaf(ws[2][ci * 3 + 2], x2, a2);
    }
    float* op = out + (size_t)bs * 3 * L + t0 + t;
    op[0]     = a0;
    op[L]     = a1;
    op[2 * L] = a2;
}

// ---------------- valid mask: any(targets[b,:,:,s] != 0) -------------------
__global__ void valid_kernel(const float* __restrict__ targets)
{
    const int bs = blockIdx.x, b = bs >> 2, s = bs & 3;
    __shared__ int any_nz;
    if (threadIdx.x == 0) any_nz = 0;
    __syncthreads();
    int local = 0;
    for (int i = threadIdx.x; i < 3 * TOUT; i += blockDim.x) {
        int c = i / TOUT, t = i % TOUT;
        if (targets[((size_t)(b * 3 + c) * TOUT + t) * 4 + s] != 0.0f) { local = 1; break; }
    }
    if (local) atomicOr(&any_nz, 1);
    __syncthreads();
    if (threadIdx.x == 0 && any_nz) atomicAdd(&g_valid, 1);
}

// ---------------- transpose-write x + masked CE partial sums ---------------
__global__ __launch_bounds__(256) void loss_kernel(
    const float* __restrict__ targets, float* __restrict__ dout)
{
    const int bs = blockIdx.y, b = bs >> 2, s = bs & 3;
    const int t  = blockIdx.x * 256 + threadIdx.x;
    const float* y = g_buf5 + (size_t)bs * 3 * TOUT;
    float y0 = y[t], y1 = y[TOUT + t], y2 = y[2 * TOUT + t];

    // out layout [bt,3,T,st]; c-stride = TOUT*4 elements. targets share layout.
    size_t o0 = ((size_t)(b * 3) * TOUT + t) * 4 + s;
    const size_t cs = (size_t)TOUT * 4;
    dout[o0]          = y0;
    dout[o0 + cs]     = y1;
    dout[o0 + 2 * cs] = y2;

    float m   = fmaxf(y0, fmaxf(y1, y2));
    float lse = m + logf(expf(y0 - m) + expf(y1 - m) + expf(y2 - m));
    float t0v = targets[o0], t1v = targets[o0 + cs], t2v = targets[o0 + 2 * cs];
    float part = t0v * (lse - y0) + t1v * (lse - y1) + t2v * (lse - y2);

    __shared__ float red[256];
    red[threadIdx.x] = part;
    __syncthreads();
#pragma unroll
    for (int o = 128; o > 0; o >>= 1) {
        if (threadIdx.x < o) red[threadIdx.x] += red[threadIdx.x + o];
        __syncthreads();
    }
    if (threadIdx.x == 0) atomicAdd(&g_loss_acc, (double)red[0]);
}

__global__ void finalize_kernel(float* __restrict__ dout)
{
    dout[(size_t)BT * 3 * TOUT * ST] =
        (float)(g_loss_acc / ((double)g_valid * (double)TOUT));
}

// ---------------------------------------------------------------------------
extern "C" void kernel_launch(void* const* d_in, const int* in_sizes, int n_in,
                              void* d_out, int out_size)
{
    const float* fusion  = (const float*)d_in[0];
    const float* targets = (const float*)d_in[1];
    const float* w1      = (const float*)d_in[2];
    const float* g1 = (const float*)d_in[3];
    const float* b1 = (const float*)d_in[4];
    const float* m1 = (const float*)d_in[5];
    const float* v1 = (const float*)d_in[6];
    const float* w2      = (const float*)d_in[7];
    const float* g2 = (const float*)d_in[8];
    const float* b2 = (const float*)d_in[9];
    const float* m2 = (const float*)d_in[10];
    const float* v2 = (const float*)d_in[11];
    const float* w_out   = (const float*)d_in[12];
    const float* b_out   = (const float*)d_in[13];
    float* out = (float*)d_out;

    float *p1, *p2, *p3, *p4, *p5;
    cudaGetSymbolAddress((void**)&p1, g_buf1);
    cudaGetSymbolAddress((void**)&p2, g_buf2);
    cudaGetSymbolAddress((void**)&p3, g_buf3);
    cudaGetSymbolAddress((void**)&p4, g_buf4);
    cudaGetSymbolAddress((void**)&p5, g_buf5);

    init_kernel<<<1, 1>>>();

    // conv1: 512->256, L=1024, dil=8.  Tile 64co x 64t, 4x4/thread.
    convbn_kernel<CH, C1, L1, 8, 4, 4>
        <<<dim3(L1 / 64, C1 / 64, NB), 256>>>(fusion, w1, g1, b1, m1, v1, p1);

    {   // upsample1: [64*256,1024] -> 2048
        int nc = NB * C1, total = nc * L1U;
        upsample_kernel<<<(total + 255) / 256, 256>>>(p1, p2, nc, L1);
    }

    // conv2: 256->32, L=2048, dil=16. Tile 32co x 64t, 2x4/thread.
    convbn_kernel<C1, C2, L1U, 16, 2, 4>
        <<<dim3(L1U / 64, 1, NB), 256>>>(p2, w2, g2, b2, m2, v2, p3);

    {   // upsample2: [64*32,2048] -> 4096
        int nc = NB * C2, total = nc * L2U;
        upsample_kernel<<<(total + 255) / 256, 256>>>(p3, p4, nc, L1U);
    }

    // conv_out: 32->3, L=4096, dil=32, +bias
    conv_out_kernel<<<dim3(L2U / 256, NB), 256>>>(p4, w_out, b_out, p5);

    valid_kernel<<<NB, 256>>>(targets);
    loss_kernel<<<dim3(TOUT / 256, NB), 256>>>(targets, out);
    finalize_kernel<<<1, 1>>>(out);
}

// round 2
// speedup vs baseline: 1.4931x; 1.4931x over previous
#include <cuda_runtime.h>
#include <math.h>

#define BT 16
#define ST 4
#define NB (BT*ST)
#define CH 512
#define C1 256
#define C2 32
#define L1 1024
#define L1U 2048
#define L2U 4096
#define TOUT 4096

// ---------------- scratch ---------------------------------------------------
__device__ float g_buf1[NB*C1*L1];
__device__ float g_buf2[NB*C1*L1U];
__device__ float g_buf3[NB*C2*L1U];
__device__ float g_buf4[NB*C2*L2U];
__device__ float g_buf5[NB*3*TOUT];
__device__ double g_loss_acc;
__device__ int    g_valid;

__global__ void init_kernel() { g_loss_acc = 0.0; g_valid = 0; }

// ---------------- packed f32x2 helpers -------------------------------------
typedef unsigned long long ull;

__device__ __forceinline__ void ffma2(ull &acc, ull a, ull b) {
    asm("fma.rn.f32x2 %0, %1, %2, %0;" : "+l"(acc) : "l"(a), "l"(b));
}
__device__ __forceinline__ ull packf2(float a, float b) {
    ull r; asm("mov.b64 %0, {%1, %2};" : "=l"(r) : "f"(a), "f"(b)); return r;
}
__device__ __forceinline__ float2 unpackf2(ull v) {
    float2 r; asm("mov.b64 {%0, %1}, %2;" : "=f"(r.x), "=f"(r.y) : "l"(v)); return r;
}

// ---------------- fused conv1d(reflect,dilated) + BN + ReLU, f32x2 ---------
// Block 256 threads: tx = tid&31 spans 32*4=128 time points (T_PER=4 = 2 f32x2
// pairs), ty = tid>>5 spans 8*CO_PER output channels. Weights staged as
// duplicated (w,w) float2 so the inner loop is pure LDS.64-broadcast + FFMA2.
template<int CI, int CO, int L, int DIL, int CO_PER>
__global__ __launch_bounds__(256) void convbn_kernel(
    const float* __restrict__ x, const float* __restrict__ w,
    const float* __restrict__ gamma, const float* __restrict__ beta,
    const float* __restrict__ mean,  const float* __restrict__ var,
    float* __restrict__ out)
{
    constexpr int CI_STEP = 8;
    constexpr int T_T  = 128;
    constexpr int CO_T = 8 * CO_PER;
    constexpr int XW   = T_T + 2 * DIL;        // multiple of 16 for both convs

    __shared__ __align__(16) float xs[CI_STEP][XW];
    __shared__ __align__(16) ull   ws2[CI_STEP][3][CO_T];   // (w,w) packed

    const int b   = blockIdx.z;
    const int t0  = blockIdx.x * T_T;
    const int co0 = blockIdx.y * CO_T;
    const int tid = threadIdx.x;
    const int tx  = tid & 31;
    const int ty  = tid >> 5;

    const float* xb = x + (size_t)b * CI * L;

    ull acc2[CO_PER][2];
#pragma unroll
    for (int i = 0; i < CO_PER; i++) { acc2[i][0] = 0ull; acc2[i][1] = 0ull; }

    for (int ci0 = 0; ci0 < CI; ci0 += CI_STEP) {
        // ---- stage x (float4 fast path; reflect on edge tiles only) ----
        constexpr int NV = CI_STEP * (XW / 4);
        for (int i = tid; i < NV; i += 256) {
            int r  = i / (XW / 4);
            int c4 = (i % (XW / 4)) * 4;
            int g0 = t0 - DIL + c4;
            const float* xr = xb + (size_t)(ci0 + r) * L;
            if (g0 >= 0 && g0 + 3 < L) {
                *(float4*)&xs[r][c4] = *(const float4*)(xr + g0);
            } else {
#pragma unroll
                for (int j = 0; j < 4; j++) {
                    int g = g0 + j;
                    g = (g < 0) ? -g : ((g >= L) ? 2 * L - 2 - g : g);
                    xs[r][c4 + j] = xr[g];
                }
            }
        }
        // ---- stage weights, duplicated, coalesced over ci ----
        for (int i = tid; i < CI_STEP * CO_T; i += 256) {
            int co = i / CI_STEP;
            int ci = i % CI_STEP;
            const float* wp = w + ((size_t)(co0 + co) * CI + ci0 + ci) * 3;
#pragma unroll
            for (int k = 0; k < 3; k++) {
                float v = wp[k];
                ws2[ci][k][co] = packf2(v, v);
            }
        }
        __syncthreads();

#pragma unroll
        for (int ci = 0; ci < CI_STEP; ci++) {
            ull xlo[3], xhi[3];
#pragma unroll
            for (int k = 0; k < 3; k++) {
                float4 v = *(const float4*)&xs[ci][tx * 4 + k * DIL];
                xlo[k] = packf2(v.x, v.y);
                xhi[k] = packf2(v.z, v.w);
            }
#pragma unroll
            for (int k = 0; k < 3; k++) {
#pragma unroll
                for (int i = 0; i < CO_PER; i++) {
                    ull wv = ws2[ci][k][ty * CO_PER + i];   // warp-broadcast
                    ffma2(acc2[i][0], wv, xlo[k]);
                    ffma2(acc2[i][1], wv, xhi[k]);
                }
            }
        }
        __syncthreads();
    }

    // ---- epilogue: BN(eval) + ReLU, float4 stores ----
#pragma unroll
    for (int i = 0; i < CO_PER; i++) {
        int co = co0 + ty * CO_PER + i;
        float inv = gamma[co] / sqrtf(var[co] + 1e-5f);
        float add = beta[co] - mean[co] * inv;
        float2 v0 = unpackf2(acc2[i][0]);
        float2 v1 = unpackf2(acc2[i][1]);
        float4 o;
        o.x = fmaxf(v0.x * inv + add, 0.0f);
        o.y = fmaxf(v0.y * inv + add, 0.0f);
        o.z = fmaxf(v1.x * inv + add, 0.0f);
        o.w = fmaxf(v1.y * inv + add, 0.0f);
        *(float4*)(out + ((size_t)b * CO + co) * L + t0 + tx * 4) = o;
    }
}

// ---------------- linear 2x upsample (align_corners=False) -----------------
__global__ void upsample_kernel(const float* __restrict__ in,
                                float* __restrict__ out, int NC, int Lin)
{
    int idx = blockIdx.x * blockDim.x + threadIdx.x;
    int Lo = 2 * Lin;
    if (idx >= NC * Lo) return;
    int t = idx % Lo;
    int c = idx / Lo;
    const float* p = in + (size_t)c * Lin;
    int m = t >> 1;
    float v;
    if ((t & 1) == 0) {
        v = (m == 0) ? p[0] : fmaf(0.25f, p[m - 1], 0.75f * p[m]);
    } else {
        int m1 = (m + 1 < Lin) ? m + 1 : Lin - 1;
        v = fmaf(0.75f, p[m], 0.25f * p[m1]);
    }
    out[idx] = v;
}

// ---------------- final conv (32->3, dil=32) + bias ------------------------
__global__ __launch_bounds__(256) void conv_out_kernel(
    const float* __restrict__ x, const float* __restrict__ w,
    const float* __restrict__ bias, float* __restrict__ out)
{
    constexpr int CI = C2, L = L2U, DIL = 32, T_T = 256, XW = T_T + 2 * DIL;
    __shared__ float xs[CI][XW];
    __shared__ float ws[3][CI * 3];
    const int bs = blockIdx.y;
    const int t0 = blockIdx.x * T_T;
    const int tid = threadIdx.x;
    const float* xb = x + (size_t)bs * CI * L;

    for (int i = tid; i < CI * XW; i += 256) {
        int r = i / XW, c = i % XW;
        int g = t0 - DIL + c;
        g = (g < 0) ? -g : ((g >= L) ? 2 * L - 2 - g : g);
        xs[r][c] = xb[(size_t)r * L + g];
    }
    for (int i = tid; i < 3 * CI * 3; i += 256)
        ws[i / (CI * 3)][i % (CI * 3)] = w[i];
    __syncthreads();

    float a0 = bias[0], a1 = bias[1], a2 = bias[2];
    const int t = tid;
#pragma unroll
    for (int ci = 0; ci < CI; ci++) {
        float x0 = xs[ci][t], x1 = xs[ci][t + DIL], x2 = xs[ci][t + 2 * DIL];
        a0 = fmaf(ws[0][ci * 3 + 0], x0, a0); a0 = fmaf(ws[0][ci * 3 + 1], x1, a0); a0 = fmaf(ws[0][ci * 3 + 2], x2, a0);
        a1 = fmaf(ws[1][ci * 3 + 0], x0, a1); a1 = fmaf(ws[1][ci * 3 + 1], x1, a1); a1 = fmaf(ws[1][ci * 3 + 2], x2, a1);
        a2 = fmaf(ws[2][ci * 3 + 0], x0, a2); a2 = fmaf(ws[2][ci * 3 + 1], x1, a2); a2 = fmaf(ws[2][ci * 3 + 2], x2, a2);
    }
    float* op = out + (size_t)bs * 3 * L + t0 + t;
    op[0]     = a0;
    op[L]     = a1;
    op[2 * L] = a2;
}

// ---------------- valid mask ------------------------------------------------
__global__ void valid_kernel(const float* __restrict__ targets)
{
    const int bs = blockIdx.x, b = bs >> 2, s = bs & 3;
    __shared__ int any_nz;
    if (threadIdx.x == 0) any_nz = 0;
    __syncthreads();
    int local = 0;
    for (int i = threadIdx.x; i < 3 * TOUT; i += blockDim.x) {
        int c = i / TOUT, t = i % TOUT;
        if (targets[((size_t)(b * 3 + c) * TOUT + t) * 4 + s] != 0.0f) { local = 1; break; }
    }
    if (local) atomicOr(&any_nz, 1);
    __syncthreads();
    if (threadIdx.x == 0 && any_nz) atomicAdd(&g_valid, 1);
}

// ---------------- transpose-write + masked CE ------------------------------
__global__ __launch_bounds__(256) void loss_kernel(
    const float* __restrict__ targets, float* __restrict__ dout)
{
    const int bs = blockIdx.y, b = bs >> 2, s = bs & 3;
    const int t  = blockIdx.x * 256 + threadIdx.x;
    const float* y = g_buf5 + (size_t)bs * 3 * TOUT;
    float y0 = y[t], y1 = y[TOUT + t], y2 = y[2 * TOUT + t];

    size_t o0 = ((size_t)(b * 3) * TOUT + t) * 4 + s;
    const size_t cs = (size_t)TOUT * 4;
    dout[o0]          = y0;
    dout[o0 + cs]     = y1;
    dout[o0 + 2 * cs] = y2;

    float m   = fmaxf(y0, fmaxf(y1, y2));
    float lse = m + logf(expf(y0 - m) + expf(y1 - m) + expf(y2 - m));
    float t0v = targets[o0], t1v = targets[o0 + cs], t2v = targets[o0 + 2 * cs];
    float part = t0v * (lse - y0) + t1v * (lse - y1) + t2v * (lse - y2);

    __shared__ float red[256];
    red[threadIdx.x] = part;
    __syncthreads();
#pragma unroll
    for (int o = 128; o > 0; o >>= 1) {
        if (threadIdx.x < o) red[threadIdx.x] += red[threadIdx.x + o];
        __syncthreads();
    }
    if (threadIdx.x == 0) atomicAdd(&g_loss_acc, (double)red[0]);
}

__global__ void finalize_kernel(float* __restrict__ dout)
{
    dout[(size_t)BT * 3 * TOUT * ST] =
        (float)(g_loss_acc / ((double)g_valid * (double)TOUT));
}

// ---------------------------------------------------------------------------
extern "C" void kernel_launch(void* const* d_in, const int* in_sizes, int n_in,
                              void* d_out, int out_size)
{
    const float* fusion  = (const float*)d_in[0];
    const float* targets = (const float*)d_in[1];
    const float* w1      = (const float*)d_in[2];
    const float* g1 = (const float*)d_in[3];
    const float* b1 = (const float*)d_in[4];
    const float* m1 = (const float*)d_in[5];
    const float* v1 = (const float*)d_in[6];
    const float* w2      = (const float*)d_in[7];
    const float* g2 = (const float*)d_in[8];
    const float* b2 = (const float*)d_in[9];
    const float* m2 = (const float*)d_in[10];
    const float* v2 = (const float*)d_in[11];
    const float* w_out   = (const float*)d_in[12];
    const float* b_out   = (const float*)d_in[13];
    float* out = (float*)d_out;

    float *p1, *p2, *p3, *p4, *p5;
    cudaGetSymbolAddress((void**)&p1, g_buf1);
    cudaGetSymbolAddress((void**)&p2, g_buf2);
    cudaGetSymbolAddress((void**)&p3, g_buf3);
    cudaGetSymbolAddress((void**)&p4, g_buf4);
    cudaGetSymbolAddress((void**)&p5, g_buf5);

    init_kernel<<<1, 1>>>();

    // conv1: 512->256, L=1024, dil=8. CO_PER=8 -> 64co x 128t tile.
    convbn_kernel<CH, C1, L1, 8, 8>
        <<<dim3(L1 / 128, C1 / 64, NB), 256>>>(fusion, w1, g1, b1, m1, v1, p1);

    {   // upsample1
        int nc = NB * C1, total = nc * L1U;
        upsample_kernel<<<(total + 255) / 256, 256>>>(p1, p2, nc, L1);
    }

    // conv2: 256->32, L=2048, dil=16. CO_PER=4 -> 32co x 128t tile.
    convbn_kernel<C1, C2, L1U, 16, 4>
        <<<dim3(L1U / 128, 1, NB), 256>>>(p2, w2, g2, b2, m2, v2, p3);

    {   // upsample2
        int nc = NB * C2, total = nc * L2U;
        upsample_kernel<<<(total + 255) / 256, 256>>>(p3, p4, nc, L1U);
    }

    conv_out_kernel<<<dim3(L2U / 256, NB), 256>>>(p4, w_out, b_out, p5);

    valid_kernel<<<NB, 256>>>(targets);
    loss_kernel<<<dim3(TOUT / 256, NB), 256>>>(targets, out);
    finalize_kernel<<<1, 1>>>(out);
}

// round 8
// speedup vs baseline: 3.0842x; 2.0656x over previous
#include <cuda_runtime.h>
#include <cuda_bf16.h>
#include <math.h>

#define BT 16
#define ST 4
#define NB 64
#define CH 512
#define C1 256
#define C2 32
#define L1 1024
#define L1U 2048
#define L2U 4096
#define TOUT 4096

// ---------------- fragment-packed GEMM operands (conv1) ---------------------
// A (weights): g_wf[term(2)][ma(16)][chunk(96)][lane(32)] : uint4 (16B/lane)
//   chunk = kk*32 + cic ; fragment = w[ma*16.. +16][ci0..ci0+16] for tap kk
// B (x):       g_bf[term(2)][b(64)][ta(130)][cic(32)][lane(32)] : uint2 (8B/lane)
//   ta covers halo'd t' = t_out + (kk-1)*8, stored index ta = t_out/8 + kk
#define WF_ELEMS (2*16*96*32)
#define BF_T     ((size_t)NB*130*32*32)          // per-term uint2 count
__device__ uint4 g_wf[WF_ELEMS];
__device__ uint2 g_bf[2*BF_T];

__device__ float g_buf1[NB*C1*L1];
__device__ float g_buf2[NB*C1*L1U];
__device__ float g_buf3[NB*C2*L1U];
__device__ float g_buf4[NB*C2*L2U];
__device__ float g_buf5[NB*3*TOUT];
__device__ double g_loss_acc;
__device__ int    g_valid;

__global__ void init_kernel() { g_loss_acc = 0.0; g_valid = 0; }

// ---------------- helpers ---------------------------------------------------
__device__ __forceinline__ unsigned pack_bf2(float a, float b) {
    return ((unsigned)__bfloat16_as_ushort(__float2bfloat16(b)) << 16) |
           (unsigned)__bfloat16_as_ushort(__float2bfloat16(a));
}
__device__ __forceinline__ float bf_hi(float v) {
    return __bfloat162float(__float2bfloat16(v));
}

__device__ __forceinline__ void mma_bf16(float4& d, const uint4& a, const uint2& b) {
    asm("mma.sync.aligned.m16n8k16.row.col.f32.bf16.bf16.f32 "
        "{%0,%1,%2,%3},{%4,%5,%6,%7},{%8,%9},{%0,%1,%2,%3};"
        : "+f"(d.x), "+f"(d.y), "+f"(d.z), "+f"(d.w)
        : "r"(a.x), "r"(a.y), "r"(a.z), "r"(a.w), "r"(b.x), "r"(b.y));
}

// ---------------- prep: weights -> A fragments (hi/lo) ----------------------
__global__ void prep_w_kernel(const float* __restrict__ w1)
{
    int p = blockIdx.x * 256 + threadIdx.x;          // 49152 total
    int lane = p & 31;
    int chunk = (p >> 5) % 96;
    int ma    = (p >> 5) / 96;
    int kk  = chunk >> 5;
    int ci0 = (chunk & 31) * 16;
    int g   = lane >> 2;
    int t2  = (lane & 3) * 2;
    int coA = ma * 16 + g;          // rows g and g+8
    int coB = coA + 8;
    int k0  = ci0 + t2;

    float wA0 = w1[((size_t)coA * CH + k0)     * 3 + kk];
    float wA1 = w1[((size_t)coA * CH + k0 + 1) * 3 + kk];
    float wA8 = w1[((size_t)coA * CH + k0 + 8) * 3 + kk];
    float wA9 = w1[((size_t)coA * CH + k0 + 9) * 3 + kk];
    float wB0 = w1[((size_t)coB * CH + k0)     * 3 + kk];
    float wB1 = w1[((size_t)coB * CH + k0 + 1) * 3 + kk];
    float wB8 = w1[((size_t)coB * CH + k0 + 8) * 3 + kk];
    float wB9 = w1[((size_t)coB * CH + k0 + 9) * 3 + kk];

    uint4 hi, lo;
    hi.x = pack_bf2(wA0, wA1);
    hi.y = pack_bf2(wB0, wB1);
    hi.z = pack_bf2(wA8, wA9);
    hi.w = pack_bf2(wB8, wB9);
    lo.x = pack_bf2(wA0 - bf_hi(wA0), wA1 - bf_hi(wA1));
    lo.y = pack_bf2(wB0 - bf_hi(wB0), wB1 - bf_hi(wB1));
    lo.z = pack_bf2(wA8 - bf_hi(wA8), wA9 - bf_hi(wA9));
    lo.w = pack_bf2(wB8 - bf_hi(wB8), wB9 - bf_hi(wB9));

    size_t idx = ((size_t)ma * 96 + chunk) * 32 + lane;
    g_wf[idx] = hi;
    g_wf[(size_t)16 * 96 * 32 + idx] = lo;
}

// ---------------- prep: x -> B fragments (hi/lo), reflect halo --------------
// One CTA per (cic, b): stages the 16-ci x 1024-t slab, emits 130 ta frags.
__global__ __launch_bounds__(256) void prep_x_kernel(const float* __restrict__ fusion)
{
    extern __shared__ float st[];                    // [1024][17]
    const int cic = blockIdx.x, b = blockIdx.y;
    const int tid = threadIdx.x;
    const float* fb = fusion + ((size_t)b * CH + cic * 16) * L1;

    for (int i = tid; i < 16 * 256; i += 256) {
        int ci = i >> 8, t4 = (i & 255) * 4;
        float4 v = *(const float4*)(fb + (size_t)ci * L1 + t4);
        st[(t4 + 0) * 17 + ci] = v.x;
        st[(t4 + 1) * 17 + ci] = v.y;
        st[(t4 + 2) * 17 + ci] = v.z;
        st[(t4 + 3) * 17 + ci] = v.w;
    }
    __syncthreads();

    const int lane = tid & 31, wid = tid >> 5;
    const int g = lane >> 2, t2 = (lane & 3) * 2;
    for (int ta = wid; ta < 130; ta += 8) {
        int ts = ta * 8 + g - 8;
        ts = (ts < 0) ? -ts : ((ts >= L1) ? 2 * L1 - 2 - ts : ts);
        const float* row = st + (size_t)ts * 17;
        float v0 = row[t2], v1 = row[t2 + 1], v2 = row[t2 + 8], v3 = row[t2 + 9];
        uint2 hi, lo;
        hi.x = pack_bf2(v0, v1);
        hi.y = pack_bf2(v2, v3);
        lo.x = pack_bf2(v0 - bf_hi(v0), v1 - bf_hi(v1));
        lo.y = pack_bf2(v2 - bf_hi(v2), v3 - bf_hi(v3));
        size_t idx = (((size_t)b * 130 + ta) * 32 + cic) * 32 + lane;
        g_bf[idx] = hi;
        g_bf[BF_T + idx] = lo;
    }
}

// ---------------- conv1: warp-MMA implicit GEMM + BN + ReLU -----------------
// CTA 256 thr = 8 warps (4 co x 2 t). Warp tile m32 x n64. 3-term bf16 split.
__global__ __launch_bounds__(256) void conv1_mma_kernel(
    const float* __restrict__ gamma, const float* __restrict__ beta,
    const float* __restrict__ mean,  const float* __restrict__ var,
    float* __restrict__ out)
{
    const int tid = threadIdx.x, lane = tid & 31, wid = tid >> 5;
    const int wy = wid & 3, wx = wid >> 2;
    const int tb = blockIdx.x, cbk = blockIdx.y, b = blockIdx.z;
    const int ma0 = cbk * 8 + wy * 2;                // m-atom base (16-co units)
    const int ta0 = tb * 16 + wx * 8;                // n-atom base (8-t units)

    const char* ab = (const char*)g_wf + ((size_t)ma0 * 96) * 32 * 16 + (size_t)lane * 16;
    const char* bh = (const char*)g_bf + (((size_t)b * 130 + ta0) * 32) * 32 * 8 + (size_t)lane * 8;
    const char* bl = bh + BF_T * 8;

    float4 d[2][8];
#pragma unroll
    for (int m = 0; m < 2; m++)
#pragma unroll
        for (int n = 0; n < 8; n++) d[m][n] = make_float4(0.f, 0.f, 0.f, 0.f);

    // prime current fragments
    uint4 Ah0 = *(const uint4*)(ab);
    uint4 Ah1 = *(const uint4*)(ab + 49152);
    uint4 Al0 = *(const uint4*)(ab + 786432);
    uint4 Al1 = *(const uint4*)(ab + 786432 + 49152);
    uint2 Bh[8], Bl[8];
#pragma unroll
    for (int n = 0; n < 8; n++) {
        Bh[n] = *(const uint2*)(bh + n * 8192);
        Bl[n] = *(const uint2*)(bl + n * 8192);
    }

#pragma unroll 1
    for (int c = 0; c < 96; c++) {
        ab += 512; bh += 256; bl += 256;
        uint4 nAh0, nAh1, nAl0, nAl1;
        uint2 nBh[8], nBl[8];
        if (c < 95) {
            nAh0 = *(const uint4*)(ab);
            nAh1 = *(const uint4*)(ab + 49152);
            nAl0 = *(const uint4*)(ab + 786432);
            nAl1 = *(const uint4*)(ab + 786432 + 49152);
#pragma unroll
            for (int n = 0; n < 8; n++) {
                nBh[n] = *(const uint2*)(bh + n * 8192);
                nBl[n] = *(const uint2*)(bl + n * 8192);
            }
        }
        // hh
#pragma unroll
        for (int n = 0; n < 8; n++) {
            mma_bf16(d[0][n], Ah0, Bh[n]);
            mma_bf16(d[1][n], Ah1, Bh[n]);
        }
        // hl
#pragma unroll
        for (int n = 0; n < 8; n++) {
            mma_bf16(d[0][n], Ah0, Bl[n]);
            mma_bf16(d[1][n], Ah1, Bl[n]);
        }
        // lh
#pragma unroll
        for (int n = 0; n < 8; n++) {
            mma_bf16(d[0][n], Al0, Bh[n]);
            mma_bf16(d[1][n], Al1, Bh[n]);
        }
        if (c < 95) {
            Ah0 = nAh0; Ah1 = nAh1; Al0 = nAl0; Al1 = nAl1;
#pragma unroll
            for (int n = 0; n < 8; n++) { Bh[n] = nBh[n]; Bl[n] = nBl[n]; }
        }
    }

    // epilogue: BN + ReLU, float2 stores
    const int g = lane >> 2, t2 = (lane & 3) * 2;
    const int tbase = tb * 128 + wx * 64 + t2;
#pragma unroll
    for (int m = 0; m < 2; m++) {
        int coA = cbk * 128 + (wy * 2 + m) * 16 + g;
        int coB = coA + 8;
        float invA = gamma[coA] / sqrtf(var[coA] + 1e-5f);
        float addA = beta[coA] - mean[coA] * invA;
        float invB = gamma[coB] / sqrtf(var[coB] + 1e-5f);
        float addB = beta[coB] - mean[coB] * invB;
        float* oA = out + ((size_t)(b * C1 + coA)) * L1 + tbase;
        float* oB = out + ((size_t)(b * C1 + coB)) * L1 + tbase;
#pragma unroll
        for (int n = 0; n < 8; n++) {
            float2 vA, vB;
            vA.x = fmaxf(d[m][n].x * invA + addA, 0.0f);
            vA.y = fmaxf(d[m][n].y * invA + addA, 0.0f);
            vB.x = fmaxf(d[m][n].z * invB + addB, 0.0f);
            vB.y = fmaxf(d[m][n].w * invB + addB, 0.0f);
            *(float2*)(oA + n * 8) = vA;
            *(float2*)(oB + n * 8) = vB;
        }
    }
}

// ---------------- packed f32x2 helpers (conv2) ------------------------------
typedef unsigned long long ull;
__device__ __forceinline__ void ffma2(ull &acc, ull a, ull b) {
    asm("fma.rn.f32x2 %0, %1, %2, %0;" : "+l"(acc) : "l"(a), "l"(b));
}
__device__ __forceinline__ ull packf2(float a, float b) {
    ull r; asm("mov.b64 %0, {%1, %2};" : "=l"(r) : "f"(a), "f"(b)); return r;
}
__device__ __forceinline__ float2 unpackf2(ull v) {
    float2 r; asm("mov.b64 {%0, %1}, %2;" : "=f"(r.x), "=f"(r.y) : "l"(v)); return r;
}

// ---------------- conv2: fused conv+BN+ReLU, f32x2 -------------------------
template<int CI, int CO, int L, int DIL, int CO_PER, int NT>
__global__ __launch_bounds__(NT) void convbn_kernel(
    const float* __restrict__ x, const float* __restrict__ w,
    const float* __restrict__ gamma, const float* __restrict__ beta,
    const float* __restrict__ mean,  const float* __restrict__ var,
    float* __restrict__ out)
{
    constexpr int CI_STEP = 8;
    constexpr int T_T  = 128;
    constexpr int CO_T = (NT / 32) * CO_PER;
    constexpr int XW   = T_T + 2 * DIL;

    __shared__ __align__(16) float xs[CI_STEP][XW];
    __shared__ __align__(16) ull   ws2[CI_STEP][3][CO_T];

    const int b   = blockIdx.z;
    const int t0  = blockIdx.x * T_T;
    const int co0 = blockIdx.y * CO_T;
    const int tid = threadIdx.x;
    const int tx  = tid & 31;
    const int ty  = tid >> 5;

    const float* xb = x + (size_t)b * CI * L;

    ull acc2[CO_PER][2];
#pragma unroll
    for (int i = 0; i < CO_PER; i++) { acc2[i][0] = 0ull; acc2[i][1] = 0ull; }

    for (int ci0 = 0; ci0 < CI; ci0 += CI_STEP) {
        constexpr int NV = CI_STEP * (XW / 4);
        for (int i = tid; i < NV; i += NT) {
            int r  = i / (XW / 4);
            int c4 = (i % (XW / 4)) * 4;
            int g0 = t0 - DIL + c4;
            const float* xr = xb + (size_t)(ci0 + r) * L;
            if (g0 >= 0 && g0 + 3 < L) {
                *(float4*)&xs[r][c4] = *(const float4*)(xr + g0);
            } else {
#pragma unroll
                for (int j = 0; j < 4; j++) {
                    int gg = g0 + j;
                    gg = (gg < 0) ? -gg : ((gg >= L) ? 2 * L - 2 - gg : gg);
                    xs[r][c4 + j] = xr[gg];
                }
            }
        }
        for (int i = tid; i < CI_STEP * CO_T; i += NT) {
            int co = i / CI_STEP;
            int ci = i % CI_STEP;
            const float* wp = w + ((size_t)(co0 + co) * CI + ci0 + ci) * 3;
#pragma unroll
            for (int k = 0; k < 3; k++) {
                float v = wp[k];
                ws2[ci][k][co] = packf2(v, v);
            }
        }
        __syncthreads();

#pragma unroll
        for (int ci = 0; ci < CI_STEP; ci++) {
            ull xlo[3], xhi[3];
#pragma unroll
            for (int k = 0; k < 3; k++) {
                float4 v = *(const float4*)&xs[ci][tx * 4 + k * DIL];
                xlo[k] = packf2(v.x, v.y);
                xhi[k] = packf2(v.z, v.w);
            }
#pragma unroll
            for (int k = 0; k < 3; k++) {
#pragma unroll
                for (int i = 0; i < CO_PER; i++) {
                    ull wv = ws2[ci][k][ty * CO_PER + i];
                    ffma2(acc2[i][0], wv, xlo[k]);
                    ffma2(acc2[i][1], wv, xhi[k]);
                }
            }
        }
        __syncthreads();
    }

#pragma unroll
    for (int i = 0; i < CO_PER; i++) {
        int co = co0 + ty * CO_PER + i;
        float inv = gamma[co] / sqrtf(var[co] + 1e-5f);
        float add = beta[co] - mean[co] * inv;
        float2 v0 = unpackf2(acc2[i][0]);
        float2 v1 = unpackf2(acc2[i][1]);
        float4 o;
        o.x = fmaxf(v0.x * inv + add, 0.0f);
        o.y = fmaxf(v0.y * inv + add, 0.0f);
        o.z = fmaxf(v1.x * inv + add, 0.0f);
        o.w = fmaxf(v1.y * inv + add, 0.0f);
        *(float4*)(out + ((size_t)b * CO + co) * L + t0 + tx * 4) = o;
    }
}

// ---------------- linear 2x upsample ---------------------------------------
__global__ void upsample_kernel(const float* __restrict__ in,
                                float* __restrict__ out, int NC, int Lin)
{
    int idx = blockIdx.x * blockDim.x + threadIdx.x;
    int Lo = 2 * Lin;
    if (idx >= NC * Lo) return;
    int t = idx % Lo;
    int c = idx / Lo;
    const float* p = in + (size_t)c * Lin;
    int m = t >> 1;
    float v;
    if ((t & 1) == 0) {
        v = (m == 0) ? p[0] : fmaf(0.25f, p[m - 1], 0.75f * p[m]);
    } else {
        int m1 = (m + 1 < Lin) ? m + 1 : Lin - 1;
        v = fmaf(0.75f, p[m], 0.25f * p[m1]);
    }
    out[idx] = v;
}

// ---------------- final conv (32->3, dil=32) + bias ------------------------
__global__ __launch_bounds__(256) void conv_out_kernel(
    const float* __restrict__ x, const float* __restrict__ w,
    const float* __restrict__ bias, float* __restrict__ out)
{
    constexpr int CI = C2, L = L2U, DIL = 32, T_T = 256, XW = T_T + 2 * DIL;
    __shared__ float xs[CI][XW];
    __shared__ float ws[3][CI * 3];
    const int bs = blockIdx.y;
    const int t0 = blockIdx.x * T_T;
    const int tid = threadIdx.x;
    const float* xb = x + (size_t)bs * CI * L;

    for (int i = tid; i < CI * XW; i += 256) {
        int r = i / XW, c = i % XW;
        int g = t0 - DIL + c;
        g = (g < 0) ? -g : ((g >= L) ? 2 * L - 2 - g : g);
        xs[r][c] = xb[(size_t)r * L + g];
    }
    for (int i = tid; i < 3 * CI * 3; i += 256)
        ws[i / (CI * 3)][i % (CI * 3)] = w[i];
    __syncthreads();

    float a0 = bias[0], a1 = bias[1], a2 = bias[2];
    const int t = tid;
#pragma unroll
    for (int ci = 0; ci < CI; ci++) {
        float x0 = xs[ci][t], x1 = xs[ci][t + DIL], x2 = xs[ci][t + 2 * DIL];
        a0 = fmaf(ws[0][ci * 3 + 0], x0, a0); a0 = fmaf(ws[0][ci * 3 + 1], x1, a0); a0 = fmaf(ws[0][ci * 3 + 2], x2, a0);
        a1 = fmaf(ws[1][ci * 3 + 0], x0, a1); a1 = fmaf(ws[1][ci * 3 + 1], x1, a1); a1 = fmaf(ws[1][ci * 3 + 2], x2, a1);
        a2 = fmaf(ws[2][ci * 3 + 0], x0, a2); a2 = fmaf(ws[2][ci * 3 + 1], x1, a2); a2 = fmaf(ws[2][ci * 3 + 2], x2, a2);
    }
    float* op = out + (size_t)bs * 3 * L + t0 + t;
    op[0]     = a0;
    op[L]     = a1;
    op[2 * L] = a2;
}

// ---------------- valid mask ------------------------------------------------
__global__ void valid_kernel(const float* __restrict__ targets)
{
    const int bs = blockIdx.x, b = bs >> 2, s = bs & 3;
    __shared__ int any_nz;
    if (threadIdx.x == 0) any_nz = 0;
    __syncthreads();
    int local = 0;
    for (int i = threadIdx.x; i < 3 * TOUT; i += blockDim.x) {
        int c = i / TOUT, t = i % TOUT;
        if (targets[((size_t)(b * 3 + c) * TOUT + t) * 4 + s] != 0.0f) { local = 1; break; }
    }
    if (local) atomicOr(&any_nz, 1);
    __syncthreads();
    if (threadIdx.x == 0 && any_nz) atomicAdd(&g_valid, 1);
}

// ---------------- transpose-write + masked CE ------------------------------
__global__ __launch_bounds__(256) void loss_kernel(
    const float* __restrict__ targets, float* __restrict__ dout)
{
    const int bs = blockIdx.y, b = bs >> 2, s = bs & 3;
    const int t  = blockIdx.x * 256 + threadIdx.x;
    const float* y = g_buf5 + (size_t)bs * 3 * TOUT;
    float y0 = y[t], y1 = y[TOUT + t], y2 = y[2 * TOUT + t];

    size_t o0 = ((size_t)(b * 3) * TOUT + t) * 4 + s;
    const size_t cs = (size_t)TOUT * 4;
    dout[o0]          = y0;
    dout[o0 + cs]     = y1;
    dout[o0 + 2 * cs] = y2;

    float m   = fmaxf(y0, fmaxf(y1, y2));
    float lse = m + logf(expf(y0 - m) + expf(y1 - m) + expf(y2 - m));
    float t0v = targets[o0], t1v = targets[o0 + cs], t2v = targets[o0 + 2 * cs];
    float part = t0v * (lse - y0) + t1v * (lse - y1) + t2v * (lse - y2);

    __shared__ float red[256];
    red[threadIdx.x] = part;
    __syncthreads();
#pragma unroll
    for (int o = 128; o > 0; o >>= 1) {
        if (threadIdx.x < o) red[threadIdx.x] += red[threadIdx.x + o];
        __syncthreads();
    }
    if (threadIdx.x == 0) atomicAdd(&g_loss_acc, (double)red[0]);
}

__global__ void finalize_kernel(float* __restrict__ dout)
{
    dout[(size_t)BT * 3 * TOUT * ST] =
        (float)(g_loss_acc / ((double)g_valid * (double)TOUT));
}

// ---------------------------------------------------------------------------
extern "C" void kernel_launch(void* const* d_in, const int* in_sizes, int n_in,
                              void* d_out, int out_size)
{
    const float* fusion  = (const float*)d_in[0];
    const float* targets = (const float*)d_in[1];
    const float* w1      = (const float*)d_in[2];
    const float* g1 = (const float*)d_in[3];
    const float* b1 = (const float*)d_in[4];
    const float* m1 = (const float*)d_in[5];
    const float* v1 = (const float*)d_in[6];
    const float* w2      = (const float*)d_in[7];
    const float* g2 = (const float*)d_in[8];
    const float* b2 = (const float*)d_in[9];
    const float* m2 = (const float*)d_in[10];
    const float* v2 = (const float*)d_in[11];
    const float* w_out   = (const float*)d_in[12];
    const float* b_out   = (const float*)d_in[13];
    float* out = (float*)d_out;

    float *p1, *p2, *p3, *p4, *p5;
    cudaGetSymbolAddress((void**)&p1, g_buf1);
    cudaGetSymbolAddress((void**)&p2, g_buf2);
    cudaGetSymbolAddress((void**)&p3, g_buf3);
    cudaGetSymbolAddress((void**)&p4, g_buf4);
    cudaGetSymbolAddress((void**)&p5, g_buf5);

    static int smem_set = 0;
    if (!smem_set) {
        cudaFuncSetAttribute(prep_x_kernel,
                             cudaFuncAttributeMaxDynamicSharedMemorySize, 69632);
        smem_set = 1;
    }

    init_kernel<<<1, 1>>>();
    prep_w_kernel<<<192, 256>>>(w1);
    prep_x_kernel<<<dim3(32, NB), 256, 69632>>>(fusion);

    // conv1: warp-MMA implicit GEMM. grid (t-blocks 8, co-blocks 2, batch 64)
    conv1_mma_kernel<<<dim3(L1 / 128, C1 / 128, NB), 256>>>(g1, b1, m1, v1, p1);

    {   // upsample1
        int nc = NB * C1, total = nc * L1U;
        upsample_kernel<<<(total + 255) / 256, 256>>>(p1, p2, nc, L1);
    }

    // conv2: 256->32, L=2048, dil=16. NT=128, CO_PER=8 -> 32co x 128t tile.
    convbn_kernel<C1, C2, L1U, 16, 8, 128>
        <<<dim3(L1U / 128, 1, NB), 128>>>(p2, w2, g2, b2, m2, v2, p3);

    {   // upsample2
        int nc = NB * C2, total = nc * L2U;
        upsample_kernel<<<(total + 255) / 256, 256>>>(p3, p4, nc, L1U);
    }

    conv_out_kernel<<<dim3(L2U / 256, NB), 256>>>(p4, w_out, b_out, p5);

    valid_kernel<<<NB, 256>>>(targets);
    loss_kernel<<<dim3(TOUT / 256, NB), 256>>>(targets, out);
    finalize_kernel<<<1, 1>>>(out);
}

// round 11
// speedup vs baseline: 3.6962x; 1.1984x over previous
#include <cuda_runtime.h>
#include <cuda_bf16.h>
#include <math.h>

#define BT 16
#define ST 4
#define NB 64
#define CH 512
#define C1 256
#define C2 32
#define L1 1024
#define L1U 2048
#define L2U 4096
#define TOUT 4096

// ---------------- fragment-packed GEMM operands (conv1) ---------------------
// A (weights): g_wf[term(2)][ma(16)][chunk(96)][lane(32)] : uint4 (16B/lane)
// B (x):       g_bf[term(2)][b(64)][ta(130)][cic(32)][lane(32)] : uint2 (8B/lane)
#define WF_ELEMS (2*16*96*32)
#define BF_T     ((size_t)NB*130*32*32)          // per-term uint2 count
__device__ uint4 g_wf[WF_ELEMS];
__device__ uint2 g_bf[2*BF_T];

__device__ float g_buf1[NB*C1*L1];
__device__ float g_buf2[NB*C1*L1U];
__device__ float g_buf3[NB*C2*L1U];
__device__ float g_buf4[NB*C2*L2U];
__device__ float g_buf5[NB*3*TOUT];
__device__ double g_loss_acc;
__device__ int    g_valid;

__global__ void init_kernel() { g_loss_acc = 0.0; g_valid = 0; }

// ---------------- helpers ---------------------------------------------------
__device__ __forceinline__ unsigned pack_bf2(float a, float b) {
    return ((unsigned)__bfloat16_as_ushort(__float2bfloat16(b)) << 16) |
           (unsigned)__bfloat16_as_ushort(__float2bfloat16(a));
}
__device__ __forceinline__ float bf_hi(float v) {
    return __bfloat162float(__float2bfloat16(v));
}

__device__ __forceinline__ void mma_bf16(float4& d, const uint4& a, const uint2& b) {
    asm("mma.sync.aligned.m16n8k16.row.col.f32.bf16.bf16.f32 "
        "{%0,%1,%2,%3},{%4,%5,%6,%7},{%8,%9},{%0,%1,%2,%3};"
        : "+f"(d.x), "+f"(d.y), "+f"(d.z), "+f"(d.w)
        : "r"(a.x), "r"(a.y), "r"(a.z), "r"(a.w), "r"(b.x), "r"(b.y));
}

// ---------------- prep: weights -> A fragments (hi/lo) ----------------------
__global__ void prep_w_kernel(const float* __restrict__ w1)
{
    int p = blockIdx.x * 256 + threadIdx.x;          // 49152 total
    int lane = p & 31;
    int chunk = (p >> 5) % 96;
    int ma    = (p >> 5) / 96;
    int kk  = chunk >> 5;
    int ci0 = (chunk & 31) * 16;
    int g   = lane >> 2;
    int t2  = (lane & 3) * 2;
    int coA = ma * 16 + g;
    int coB = coA + 8;
    int k0  = ci0 + t2;

    float wA0 = w1[((size_t)coA * CH + k0)     * 3 + kk];
    float wA1 = w1[((size_t)coA * CH + k0 + 1) * 3 + kk];
    float wA8 = w1[((size_t)coA * CH + k0 + 8) * 3 + kk];
    float wA9 = w1[((size_t)coA * CH + k0 + 9) * 3 + kk];
    float wB0 = w1[((size_t)coB * CH + k0)     * 3 + kk];
    float wB1 = w1[((size_t)coB * CH + k0 + 1) * 3 + kk];
    float wB8 = w1[((size_t)coB * CH + k0 + 8) * 3 + kk];
    float wB9 = w1[((size_t)coB * CH + k0 + 9) * 3 + kk];

    uint4 hi, lo;
    hi.x = pack_bf2(wA0, wA1);
    hi.y = pack_bf2(wB0, wB1);
    hi.z = pack_bf2(wA8, wA9);
    hi.w = pack_bf2(wB8, wB9);
    lo.x = pack_bf2(wA0 - bf_hi(wA0), wA1 - bf_hi(wA1));
    lo.y = pack_bf2(wB0 - bf_hi(wB0), wB1 - bf_hi(wB1));
    lo.z = pack_bf2(wA8 - bf_hi(wA8), wA9 - bf_hi(wA9));
    lo.w = pack_bf2(wB8 - bf_hi(wB8), wB9 - bf_hi(wB9));

    size_t idx = ((size_t)ma * 96 + chunk) * 32 + lane;
    g_wf[idx] = hi;
    g_wf[(size_t)16 * 96 * 32 + idx] = lo;
}

// ---------------- prep: x -> B fragments (hi/lo), reflect halo --------------
__global__ __launch_bounds__(256) void prep_x_kernel(const float* __restrict__ fusion)
{
    extern __shared__ float st[];                    // [1024][17]
    const int cic = blockIdx.x, b = blockIdx.y;
    const int tid = threadIdx.x;
    const float* fb = fusion + ((size_t)b * CH + cic * 16) * L1;

    for (int i = tid; i < 16 * 256; i += 256) {
        int ci = i >> 8, t4 = (i & 255) * 4;
        float4 v = *(const float4*)(fb + (size_t)ci * L1 + t4);
        st[(t4 + 0) * 17 + ci] = v.x;
        st[(t4 + 1) * 17 + ci] = v.y;
        st[(t4 + 2) * 17 + ci] = v.z;
        st[(t4 + 3) * 17 + ci] = v.w;
    }
    __syncthreads();

    const int lane = tid & 31, wid = tid >> 5;
    const int g = lane >> 2, t2 = (lane & 3) * 2;
    for (int ta = wid; ta < 130; ta += 8) {
        int ts = ta * 8 + g - 8;
        ts = (ts < 0) ? -ts : ((ts >= L1) ? 2 * L1 - 2 - ts : ts);
        const float* row = st + (size_t)ts * 17;
        float v0 = row[t2], v1 = row[t2 + 1], v2 = row[t2 + 8], v3 = row[t2 + 9];
        uint2 hi, lo;
        hi.x = pack_bf2(v0, v1);
        hi.y = pack_bf2(v2, v3);
        lo.x = pack_bf2(v0 - bf_hi(v0), v1 - bf_hi(v1));
        lo.y = pack_bf2(v2 - bf_hi(v2), v3 - bf_hi(v3));
        size_t idx = (((size_t)b * 130 + ta) * 32 + cic) * 32 + lane;
        g_bf[idx] = hi;
        g_bf[BF_T + idx] = lo;
    }
}

// ---------------- conv1: warp-MMA implicit GEMM + BN + ReLU -----------------
// 8 warps (4 co x 2 t), warp tile m32 x n64, 3-term bf16 split.
// No manual prefetch: 24 independent LDGs at loop top; latency hidden by
// 2 CTAs/SM (4 warps/SMSP).
__global__ __launch_bounds__(256, 2) void conv1_mma_kernel(
    const float* __restrict__ gamma, const float* __restrict__ beta,
    const float* __restrict__ mean,  const float* __restrict__ var,
    float* __restrict__ out)
{
    const int tid = threadIdx.x, lane = tid & 31, wid = tid >> 5;
    const int wy = wid & 3, wx = wid >> 2;
    const int tb = blockIdx.x, cbk = blockIdx.y, b = blockIdx.z;
    const int ma0 = cbk * 8 + wy * 2;
    const int ta0 = tb * 16 + wx * 8;

    const char* ab = (const char*)g_wf + ((size_t)ma0 * 96) * 32 * 16 + (size_t)lane * 16;
    const char* bh = (const char*)g_bf + (((size_t)b * 130 + ta0) * 32) * 32 * 8 + (size_t)lane * 8;
    const char* bl = bh + BF_T * 8;

    float4 d[2][8];
#pragma unroll
    for (int m = 0; m < 2; m++)
#pragma unroll
        for (int n = 0; n < 8; n++) d[m][n] = make_float4(0.f, 0.f, 0.f, 0.f);

#pragma unroll 1
    for (int c = 0; c < 96; c++) {
        uint4 Ah0 = *(const uint4*)(ab);
        uint4 Ah1 = *(const uint4*)(ab + 49152);
        uint4 Al0 = *(const uint4*)(ab + 786432);
        uint4 Al1 = *(const uint4*)(ab + 786432 + 49152);
        uint2 Bh[8], Bl[8];
#pragma unroll
        for (int n = 0; n < 8; n++) {
            Bh[n] = *(const uint2*)(bh + n * 8192);
            Bl[n] = *(const uint2*)(bl + n * 8192);
        }
        ab += 512; bh += 256; bl += 256;

        // hh
#pragma unroll
        for (int n = 0; n < 8; n++) {
            mma_bf16(d[0][n], Ah0, Bh[n]);
            mma_bf16(d[1][n], Ah1, Bh[n]);
        }
        // hl
#pragma unroll
        for (int n = 0; n < 8; n++) {
            mma_bf16(d[0][n], Ah0, Bl[n]);
            mma_bf16(d[1][n], Ah1, Bl[n]);
        }
        // lh
#pragma unroll
        for (int n = 0; n < 8; n++) {
            mma_bf16(d[0][n], Al0, Bh[n]);
            mma_bf16(d[1][n], Al1, Bh[n]);
        }
    }

    // epilogue: BN + ReLU
    const int g = lane >> 2, t2 = (lane & 3) * 2;
    const int tbase = tb * 128 + wx * 64 + t2;
#pragma unroll
    for (int m = 0; m < 2; m++) {
        int coA = cbk * 128 + (wy * 2 + m) * 16 + g;
        int coB = coA + 8;
        float invA = gamma[coA] / sqrtf(var[coA] + 1e-5f);
        float addA = beta[coA] - mean[coA] * invA;
        float invB = gamma[coB] / sqrtf(var[coB] + 1e-5f);
        float addB = beta[coB] - mean[coB] * invB;
        float* oA = out + ((size_t)(b * C1 + coA)) * L1 + tbase;
        float* oB = out + ((size_t)(b * C1 + coB)) * L1 + tbase;
#pragma unroll
        for (int n = 0; n < 8; n++) {
            float2 vA, vB;
            vA.x = fmaxf(d[m][n].x * invA + addA, 0.0f);
            vA.y = fmaxf(d[m][n].y * invA + addA, 0.0f);
            vB.x = fmaxf(d[m][n].z * invB + addB, 0.0f);
            vB.y = fmaxf(d[m][n].w * invB + addB, 0.0f);
            *(float2*)(oA + n * 8) = vA;
            *(float2*)(oB + n * 8) = vB;
        }
    }
}

// ---------------- packed f32x2 helpers (conv2) ------------------------------
typedef unsigned long long ull;
__device__ __forceinline__ void ffma2(ull &acc, ull a, ull b) {
    asm("fma.rn.f32x2 %0, %1, %2, %0;" : "+l"(acc) : "l"(a), "l"(b));
}
__device__ __forceinline__ ull packf2(float a, float b) {
    ull r; asm("mov.b64 %0, {%1, %2};" : "=l"(r) : "f"(a), "f"(b)); return r;
}
__device__ __forceinline__ float2 unpackf2(ull v) {
    float2 r; asm("mov.b64 {%0, %1}, %2;" : "=f"(r.x), "=f"(r.y) : "l"(v)); return r;
}

// ---------------- conv2: fused conv+BN+ReLU, f32x2 -------------------------
template<int CI, int CO, int L, int DIL, int CO_PER, int NT>
__global__ __launch_bounds__(NT) void convbn_kernel(
    const float* __restrict__ x, const float* __restrict__ w,
    const float* __restrict__ gamma, const float* __restrict__ beta,
    const float* __restrict__ mean,  const float* __restrict__ var,
    float* __restrict__ out)
{
    constexpr int CI_STEP = 8;
    constexpr int T_T  = 128;
    constexpr int CO_T = (NT / 32) * CO_PER;
    constexpr int XW   = T_T + 2 * DIL;

    __shared__ __align__(16) float xs[CI_STEP][XW];
    __shared__ __align__(16) ull   ws2[CI_STEP][3][CO_T];

    const int b   = blockIdx.z;
    const int t0  = blockIdx.x * T_T;
    const int co0 = blockIdx.y * CO_T;
    const int tid = threadIdx.x;
    const int tx  = tid & 31;
    const int ty  = tid >> 5;

    const float* xb = x + (size_t)b * CI * L;

    ull acc2[CO_PER][2];
#pragma unroll
    for (int i = 0; i < CO_PER; i++) { acc2[i][0] = 0ull; acc2[i][1] = 0ull; }

    for (int ci0 = 0; ci0 < CI; ci0 += CI_STEP) {
        constexpr int NV = CI_STEP * (XW / 4);
        for (int i = tid; i < NV; i += NT) {
            int r  = i / (XW / 4);
            int c4 = (i % (XW / 4)) * 4;
            int g0 = t0 - DIL + c4;
            const float* xr = xb + (size_t)(ci0 + r) * L;
            if (g0 >= 0 && g0 + 3 < L) {
                *(float4*)&xs[r][c4] = *(const float4*)(xr + g0);
            } else {
#pragma unroll
                for (int j = 0; j < 4; j++) {
                    int gg = g0 + j;
                    gg = (gg < 0) ? -gg : ((gg >= L) ? 2 * L - 2 - gg : gg);
                    xs[r][c4 + j] = xr[gg];
                }
            }
        }
        for (int i = tid; i < CI_STEP * CO_T; i += NT) {
            int co = i / CI_STEP;
            int ci = i % CI_STEP;
            const float* wp = w + ((size_t)(co0 + co) * CI + ci0 + ci) * 3;
#pragma unroll
            for (int k = 0; k < 3; k++) {
                float v = wp[k];
                ws2[ci][k][co] = packf2(v, v);
            }
        }
        __syncthreads();

#pragma unroll
        for (int ci = 0; ci < CI_STEP; ci++) {
            ull xlo[3], xhi[3];
#pragma unroll
            for (int k = 0; k < 3; k++) {
                float4 v = *(const float4*)&xs[ci][tx * 4 + k * DIL];
                xlo[k] = packf2(v.x, v.y);
                xhi[k] = packf2(v.z, v.w);
            }
#pragma unroll
            for (int k = 0; k < 3; k++) {
#pragma unroll
                for (int i = 0; i < CO_PER; i++) {
                    ull wv = ws2[ci][k][ty * CO_PER + i];
                    ffma2(acc2[i][0], wv, xlo[k]);
                    ffma2(acc2[i][1], wv, xhi[k]);
                }
            }
        }
        __syncthreads();
    }

#pragma unroll
    for (int i = 0; i < CO_PER; i++) {
        int co = co0 + ty * CO_PER + i;
        float inv = gamma[co] / sqrtf(var[co] + 1e-5f);
        float add = beta[co] - mean[co] * inv;
        float2 v0 = unpackf2(acc2[i][0]);
        float2 v1 = unpackf2(acc2[i][1]);
        float4 o;
        o.x = fmaxf(v0.x * inv + add, 0.0f);
        o.y = fmaxf(v0.y * inv + add, 0.0f);
        o.z = fmaxf(v1.x * inv + add, 0.0f);
        o.w = fmaxf(v1.y * inv + add, 0.0f);
        *(float4*)(out + ((size_t)b * CO + co) * L + t0 + tx * 4) = o;
    }
}

// ---------------- linear 2x upsample ---------------------------------------
__global__ void upsample_kernel(const float* __restrict__ in,
                                float* __restrict__ out, int NC, int Lin)
{
    int idx = blockIdx.x * blockDim.x + threadIdx.x;
    int Lo = 2 * Lin;
    if (idx >= NC * Lo) return;
    int t = idx % Lo;
    int c = idx / Lo;
    const float* p = in + (size_t)c * Lin;
    int m = t >> 1;
    float v;
    if ((t & 1) == 0) {
        v = (m == 0) ? p[0] : fmaf(0.25f, p[m - 1], 0.75f * p[m]);
    } else {
        int m1 = (m + 1 < Lin) ? m + 1 : Lin - 1;
        v = fmaf(0.75f, p[m], 0.25f * p[m1]);
    }
    out[idx] = v;
}

// ---------------- final conv (32->3, dil=32) + bias ------------------------
__global__ __launch_bounds__(256) void conv_out_kernel(
    const float* __restrict__ x, const float* __restrict__ w,
    const float* __restrict__ bias, float* __restrict__ out)
{
    constexpr int CI = C2, L = L2U, DIL = 32, T_T = 256, XW = T_T + 2 * DIL;
    __shared__ float xs[CI][XW];
    __shared__ float ws[3][CI * 3];
    const int bs = blockIdx.y;
    const int t0 = blockIdx.x * T_T;
    const int tid = threadIdx.x;
    const float* xb = x + (size_t)bs * CI * L;

    for (int i = tid; i < CI * XW; i += 256) {
        int r = i / XW, c = i % XW;
        int g = t0 - DIL + c;
        g = (g < 0) ? -g : ((g >= L) ? 2 * L - 2 - g : g);
        xs[r][c] = xb[(size_t)r * L + g];
    }
    for (int i = tid; i < 3 * CI * 3; i += 256)
        ws[i / (CI * 3)][i % (CI * 3)] = w[i];
    __syncthreads();

    float a0 = bias[0], a1 = bias[1], a2 = bias[2];
    const int t = tid;
#pragma unroll
    for (int ci = 0; ci < CI; ci++) {
        float x0 = xs[ci][t], x1 = xs[ci][t + DIL], x2 = xs[ci][t + 2 * DIL];
        a0 = fmaf(ws[0][ci * 3 + 0], x0, a0); a0 = fmaf(ws[0][ci * 3 + 1], x1, a0); a0 = fmaf(ws[0][ci * 3 + 2], x2, a0);
        a1 = fmaf(ws[1][ci * 3 + 0], x0, a1); a1 = fmaf(ws[1][ci * 3 + 1], x1, a1); a1 = fmaf(ws[1][ci * 3 + 2], x2, a1);
        a2 = fmaf(ws[2][ci * 3 + 0], x0, a2); a2 = fmaf(ws[2][ci * 3 + 1], x1, a2); a2 = fmaf(ws[2][ci * 3 + 2], x2, a2);
    }
    float* op = out + (size_t)bs * 3 * L + t0 + t;
    op[0]     = a0;
    op[L]     = a1;
    op[2 * L] = a2;
}

// ---------------- valid mask ------------------------------------------------
__global__ void valid_kernel(const float* __restrict__ targets)
{
    const int bs = blockIdx.x, b = bs >> 2, s = bs & 3;
    __shared__ int any_nz;
    if (threadIdx.x == 0) any_nz = 0;
    __syncthreads();
    int local = 0;
    for (int i = threadIdx.x; i < 3 * TOUT; i += blockDim.x) {
        int c = i / TOUT, t = i % TOUT;
        if (targets[((size_t)(b * 3 + c) * TOUT + t) * 4 + s] != 0.0f) { local = 1; break; }
    }
    if (local) atomicOr(&any_nz, 1);
    __syncthreads();
    if (threadIdx.x == 0 && any_nz) atomicAdd(&g_valid, 1);
}

// ---------------- transpose-write + masked CE ------------------------------
__global__ __launch_bounds__(256) void loss_kernel(
    const float* __restrict__ targets, float* __restrict__ dout)
{
    const int bs = blockIdx.y, b = bs >> 2, s = bs & 3;
    const int t  = blockIdx.x * 256 + threadIdx.x;
    const float* y = g_buf5 + (size_t)bs * 3 * TOUT;
    float y0 = y[t], y1 = y[TOUT + t], y2 = y[2 * TOUT + t];

    size_t o0 = ((size_t)(b * 3) * TOUT + t) * 4 + s;
    const size_t cs = (size_t)TOUT * 4;
    dout[o0]          = y0;
    dout[o0 + cs]     = y1;
    dout[o0 + 2 * cs] = y2;

    float m   = fmaxf(y0, fmaxf(y1, y2));
    float lse = m + logf(expf(y0 - m) + expf(y1 - m) + expf(y2 - m));
    float t0v = targets[o0], t1v = targets[o0 + cs], t2v = targets[o0 + 2 * cs];
    float part = t0v * (lse - y0) + t1v * (lse - y1) + t2v * (lse - y2);

    __shared__ float red[256];
    red[threadIdx.x] = part;
    __syncthreads();
#pragma unroll
    for (int o = 128; o > 0; o >>= 1) {
        if (threadIdx.x < o) red[threadIdx.x] += red[threadIdx.x + o];
        __syncthreads();
    }
    if (threadIdx.x == 0) atomicAdd(&g_loss_acc, (double)red[0]);
}

__global__ void finalize_kernel(float* __restrict__ dout)
{
    dout[(size_t)BT * 3 * TOUT * ST] =
        (float)(g_loss_acc / ((double)g_valid * (double)TOUT));
}

// ---------------------------------------------------------------------------
extern "C" void kernel_launch(void* const* d_in, const int* in_sizes, int n_in,
                              void* d_out, int out_size)
{
    const float* fusion  = (const float*)d_in[0];
    const float* targets = (const float*)d_in[1];
    const float* w1      = (const float*)d_in[2];
    const float* g1 = (const float*)d_in[3];
    const float* b1 = (const float*)d_in[4];
    const float* m1 = (const float*)d_in[5];
    const float* v1 = (const float*)d_in[6];
    const float* w2      = (const float*)d_in[7];
    const float* g2 = (const float*)d_in[8];
    const float* b2 = (const float*)d_in[9];
    const float* m2 = (const float*)d_in[10];
    const float* v2 = (const float*)d_in[11];
    const float* w_out   = (const float*)d_in[12];
    const float* b_out   = (const float*)d_in[13];
    float* out = (float*)d_out;

    float *p1, *p2, *p3, *p4, *p5;
    cudaGetSymbolAddress((void**)&p1, g_buf1);
    cudaGetSymbolAddress((void**)&p2, g_buf2);
    cudaGetSymbolAddress((void**)&p3, g_buf3);
    cudaGetSymbolAddress((void**)&p4, g_buf4);
    cudaGetSymbolAddress((void**)&p5, g_buf5);

    static int smem_set = 0;
    if (!smem_set) {
        cudaFuncSetAttribute(prep_x_kernel,
                             cudaFuncAttributeMaxDynamicSharedMemorySize, 69632);
        smem_set = 1;
    }

    init_kernel<<<1, 1>>>();
    prep_w_kernel<<<192, 256>>>(w1);
    prep_x_kernel<<<dim3(32, NB), 256, 69632>>>(fusion);

    conv1_mma_kernel<<<dim3(L1 / 128, C1 / 128, NB), 256>>>(g1, b1, m1, v1, p1);

    {   // upsample1
        int nc = NB * C1, total = nc * L1U;
        upsample_kernel<<<(total + 255) / 256, 256>>>(p1, p2, nc, L1);
    }

    convbn_kernel<C1, C2, L1U, 16, 8, 128>
        <<<dim3(L1U / 128, 1, NB), 128>>>(p2, w2, g2, b2, m2, v2, p3);

    {   // upsample2
        int nc = NB * C2, total = nc * L2U;
        upsample_kernel<<<(total + 255) / 256, 256>>>(p3, p4, nc, L1U);
    }

    conv_out_kernel<<<dim3(L2U / 256, NB), 256>>>(p4, w_out, b_out, p5);

    valid_kernel<<<NB, 256>>>(targets);
    loss_kernel<<<dim3(TOUT / 256, NB), 256>>>(targets, out);
    finalize_kernel<<<1, 1>>>(out);
}

// round 14
// speedup vs baseline: 4.9831x; 1.3482x over previous
#include <cuda_runtime.h>
#include <cuda_bf16.h>
#include <math.h>

#define BT 16
#define ST 4
#define NB 64
#define CH 512
#define C1 256
#define C2 32
#define L1 1024
#define L1U 2048
#define L2U 4096
#define TOUT 4096

// ---------------- fragment-packed GEMM operands -----------------------------
// conv1 A: g_wf[term(2)][ma(16)][chunk(96)][lane(32)] uint4
// conv1 B: g_bf[term(2)][b][ta(130)][cic(32)][lane(32)] uint2
#define WF_ELEMS (2*16*96*32)
#define BF_T     ((size_t)NB*130*32*32)
__device__ uint4 g_wf[WF_ELEMS];
__device__ uint2 g_bf[2*BF_T];

// conv2 A: g_wf2[term(2)][ma(2)][chunk(48)][lane(32)] uint4
// conv2 B: g_bf2[term(2)][b][s(260)][cic(16)][lane(32)] uint2  (s = out-atom + 2kk)
#define WF2_ELEMS (2*2*48*32)
#define BF2_T     ((size_t)NB*260*16*32)
__device__ uint4 g_wf2[WF2_ELEMS];
__device__ uint2 g_bf2[2*BF2_T];

__device__ float g_buf1[NB*C1*L1];
__device__ float g_buf3[NB*C2*L1U];
__device__ float g_buf4[NB*C2*L2U];
__device__ float g_buf5[NB*3*TOUT];
__device__ double g_loss_acc;
__device__ int    g_valid;

__global__ void init_kernel() { g_loss_acc = 0.0; g_valid = 0; }

// ---------------- helpers ---------------------------------------------------
__device__ __forceinline__ unsigned pack_bf2(float a, float b) {
    return ((unsigned)__bfloat16_as_ushort(__float2bfloat16(b)) << 16) |
           (unsigned)__bfloat16_as_ushort(__float2bfloat16(a));
}
__device__ __forceinline__ float bf_hi(float v) {
    return __bfloat162float(__float2bfloat16(v));
}
__device__ __forceinline__ void mma_bf16(float4& d, const uint4& a, const uint2& b) {
    asm("mma.sync.aligned.m16n8k16.row.col.f32.bf16.bf16.f32 "
        "{%0,%1,%2,%3},{%4,%5,%6,%7},{%8,%9},{%0,%1,%2,%3};"
        : "+f"(d.x), "+f"(d.y), "+f"(d.z), "+f"(d.w)
        : "r"(a.x), "r"(a.y), "r"(a.z), "r"(a.w), "r"(b.x), "r"(b.y));
}

// ---------------- prep: conv1 weights -> A fragments ------------------------
__global__ void prep_w_kernel(const float* __restrict__ w1)
{
    int p = blockIdx.x * 256 + threadIdx.x;
    int lane = p & 31;
    int chunk = (p >> 5) % 96;
    int ma    = (p >> 5) / 96;
    int kk  = chunk >> 5;
    int ci0 = (chunk & 31) * 16;
    int g   = lane >> 2;
    int t2  = (lane & 3) * 2;
    int coA = ma * 16 + g, coB = coA + 8;
    int k0  = ci0 + t2;

    float wA0 = w1[((size_t)coA * CH + k0)     * 3 + kk];
    float wA1 = w1[((size_t)coA * CH + k0 + 1) * 3 + kk];
    float wA8 = w1[((size_t)coA * CH + k0 + 8) * 3 + kk];
    float wA9 = w1[((size_t)coA * CH + k0 + 9) * 3 + kk];
    float wB0 = w1[((size_t)coB * CH + k0)     * 3 + kk];
    float wB1 = w1[((size_t)coB * CH + k0 + 1) * 3 + kk];
    float wB8 = w1[((size_t)coB * CH + k0 + 8) * 3 + kk];
    float wB9 = w1[((size_t)coB * CH + k0 + 9) * 3 + kk];

    uint4 hi, lo;
    hi.x = pack_bf2(wA0, wA1); hi.y = pack_bf2(wB0, wB1);
    hi.z = pack_bf2(wA8, wA9); hi.w = pack_bf2(wB8, wB9);
    lo.x = pack_bf2(wA0 - bf_hi(wA0), wA1 - bf_hi(wA1));
    lo.y = pack_bf2(wB0 - bf_hi(wB0), wB1 - bf_hi(wB1));
    lo.z = pack_bf2(wA8 - bf_hi(wA8), wA9 - bf_hi(wA9));
    lo.w = pack_bf2(wB8 - bf_hi(wB8), wB9 - bf_hi(wB9));

    size_t idx = ((size_t)ma * 96 + chunk) * 32 + lane;
    g_wf[idx] = hi;
    g_wf[(size_t)16 * 96 * 32 + idx] = lo;
}

// ---------------- prep: conv2 weights -> A fragments ------------------------
__global__ void prep_w2_kernel(const float* __restrict__ w2)
{
    int p = blockIdx.x * 256 + threadIdx.x;          // 3072 total
    if (p >= 2 * 48 * 32) return;
    int lane = p & 31;
    int chunk = (p >> 5) % 48;
    int ma    = (p >> 5) / 48;
    int kk  = chunk / 16;
    int ci0 = (chunk % 16) * 16;
    int g   = lane >> 2;
    int t2  = (lane & 3) * 2;
    int coA = ma * 16 + g, coB = coA + 8;
    int k0  = ci0 + t2;

    float wA0 = w2[((size_t)coA * C1 + k0)     * 3 + kk];
    float wA1 = w2[((size_t)coA * C1 + k0 + 1) * 3 + kk];
    float wA8 = w2[((size_t)coA * C1 + k0 + 8) * 3 + kk];
    float wA9 = w2[((size_t)coA * C1 + k0 + 9) * 3 + kk];
    float wB0 = w2[((size_t)coB * C1 + k0)     * 3 + kk];
    float wB1 = w2[((size_t)coB * C1 + k0 + 1) * 3 + kk];
    float wB8 = w2[((size_t)coB * C1 + k0 + 8) * 3 + kk];
    float wB9 = w2[((size_t)coB * C1 + k0 + 9) * 3 + kk];

    uint4 hi, lo;
    hi.x = pack_bf2(wA0, wA1); hi.y = pack_bf2(wB0, wB1);
    hi.z = pack_bf2(wA8, wA9); hi.w = pack_bf2(wB8, wB9);
    lo.x = pack_bf2(wA0 - bf_hi(wA0), wA1 - bf_hi(wA1));
    lo.y = pack_bf2(wB0 - bf_hi(wB0), wB1 - bf_hi(wB1));
    lo.z = pack_bf2(wA8 - bf_hi(wA8), wA9 - bf_hi(wA9));
    lo.w = pack_bf2(wB8 - bf_hi(wB8), wB9 - bf_hi(wB9));

    size_t idx = ((size_t)ma * 48 + chunk) * 32 + lane;
    g_wf2[idx] = hi;
    g_wf2[(size_t)2 * 48 * 32 + idx] = lo;
}

// ---------------- prep: x -> conv1 B fragments, reflect halo ----------------
__global__ __launch_bounds__(256) void prep_x_kernel(const float* __restrict__ fusion)
{
    extern __shared__ float st[];                    // [1024][17]
    const int cic = blockIdx.x, b = blockIdx.y;
    const int tid = threadIdx.x;
    const float* fb = fusion + ((size_t)b * CH + cic * 16) * L1;

    for (int i = tid; i < 16 * 256; i += 256) {
        int ci = i >> 8, t4 = (i & 255) * 4;
        float4 v = *(const float4*)(fb + (size_t)ci * L1 + t4);
        st[(t4 + 0) * 17 + ci] = v.x;
        st[(t4 + 1) * 17 + ci] = v.y;
        st[(t4 + 2) * 17 + ci] = v.z;
        st[(t4 + 3) * 17 + ci] = v.w;
    }
    __syncthreads();

    const int lane = tid & 31, wid = tid >> 5;
    const int g = lane >> 2, t2 = (lane & 3) * 2;
    for (int ta = wid; ta < 130; ta += 8) {
        int ts = ta * 8 + g - 8;
        ts = (ts < 0) ? -ts : ((ts >= L1) ? 2 * L1 - 2 - ts : ts);
        const float* row = st + (size_t)ts * 17;
        float v0 = row[t2], v1 = row[t2 + 1], v2 = row[t2 + 8], v3 = row[t2 + 9];
        uint2 hi, lo;
        hi.x = pack_bf2(v0, v1);
        hi.y = pack_bf2(v2, v3);
        lo.x = pack_bf2(v0 - bf_hi(v0), v1 - bf_hi(v1));
        lo.y = pack_bf2(v2 - bf_hi(v2), v3 - bf_hi(v3));
        size_t idx = (((size_t)b * 130 + ta) * 32 + cic) * 32 + lane;
        g_bf[idx] = hi;
        g_bf[BF_T + idx] = lo;
    }
}

// ---------------- prep: conv1-out -> upsample2x -> conv2 B fragments --------
// Fuses upsample1. Stored atom s covers upsampled t' = s*8 + g - 16.
__global__ __launch_bounds__(256) void prep_x2_kernel()
{
    extern __shared__ float st[];                    // y[m][ci] : [1024][17]
    const int cic = blockIdx.x, b = blockIdx.y;
    const int tid = threadIdx.x;
    const float* fb = g_buf1 + ((size_t)b * C1 + cic * 16) * L1;

    for (int i = tid; i < 16 * 256; i += 256) {
        int ci = i >> 8, t4 = (i & 255) * 4;
        float4 v = *(const float4*)(fb + (size_t)ci * L1 + t4);
        st[(t4 + 0) * 17 + ci] = v.x;
        st[(t4 + 1) * 17 + ci] = v.y;
        st[(t4 + 2) * 17 + ci] = v.z;
        st[(t4 + 3) * 17 + ci] = v.w;
    }
    __syncthreads();

    const int lane = tid & 31, wid = tid >> 5;
    const int g = lane >> 2, t2 = (lane & 3) * 2;
    for (int s = wid; s < 260; s += 8) {
        int tp = s * 8 + g - 16;                      // upsampled index, reflect L=2048
        tp = (tp < 0) ? -tp : ((tp >= L1U) ? 2 * L1U - 2 - tp : tp);
        int m = tp >> 1;
        float wlo, whi;  int mlo, mhi;
        if ((tp & 1) == 0) {                          // even: 0.25 y[m-1] + 0.75 y[m]
            if (m == 0) { mlo = 0; mhi = 0; wlo = 1.0f; whi = 0.0f; }
            else { mlo = m - 1; mhi = m; wlo = 0.25f; whi = 0.75f; }
        } else {                                      // odd: 0.75 y[m] + 0.25 y[m+1]
            mlo = m; mhi = (m + 1 < L1) ? m + 1 : L1 - 1; wlo = 0.75f; whi = 0.25f;
        }
        const float* rlo = st + (size_t)mlo * 17;
        const float* rhi = st + (size_t)mhi * 17;
        float v0 = wlo * rlo[t2]     + whi * rhi[t2];
        float v1 = wlo * rlo[t2 + 1] + whi * rhi[t2 + 1];
        float v2 = wlo * rlo[t2 + 8] + whi * rhi[t2 + 8];
        float v3 = wlo * rlo[t2 + 9] + whi * rhi[t2 + 9];
        uint2 hi, lo;
        hi.x = pack_bf2(v0, v1);
        hi.y = pack_bf2(v2, v3);
        lo.x = pack_bf2(v0 - bf_hi(v0), v1 - bf_hi(v1));
        lo.y = pack_bf2(v2 - bf_hi(v2), v3 - bf_hi(v3));
        size_t idx = (((size_t)b * 260 + s) * 16 + cic) * 32 + lane;
        g_bf2[idx] = hi;
        g_bf2[BF2_T + idx] = lo;
    }
}

// ---------------- conv1: warp-MMA implicit GEMM + BN + ReLU -----------------
__global__ __launch_bounds__(256, 2) void conv1_mma_kernel(
    const float* __restrict__ gamma, const float* __restrict__ beta,
    const float* __restrict__ mean,  const float* __restrict__ var,
    float* __restrict__ out)
{
    const int tid = threadIdx.x, lane = tid & 31, wid = tid >> 5;
    const int wy = wid & 3, wx = wid >> 2;
    const int tb = blockIdx.x, cbk = blockIdx.y, b = blockIdx.z;
    const int ma0 = cbk * 8 + wy * 2;
    const int ta0 = tb * 16 + wx * 8;

    const char* ab = (const char*)g_wf + ((size_t)ma0 * 96) * 32 * 16 + (size_t)lane * 16;
    const char* bh = (const char*)g_bf + (((size_t)b * 130 + ta0) * 32) * 32 * 8 + (size_t)lane * 8;
    const char* bl = bh + BF_T * 8;

    float4 d[2][8];
#pragma unroll
    for (int m = 0; m < 2; m++)
#pragma unroll
        for (int n = 0; n < 8; n++) d[m][n] = make_float4(0.f, 0.f, 0.f, 0.f);

#pragma unroll 1
    for (int c = 0; c < 96; c++) {
        uint4 Ah0 = *(const uint4*)(ab);
        uint4 Ah1 = *(const uint4*)(ab + 49152);
        uint4 Al0 = *(const uint4*)(ab + 786432);
        uint4 Al1 = *(const uint4*)(ab + 786432 + 49152);
        uint2 Bh[8], Bl[8];
#pragma unroll
        for (int n = 0; n < 8; n++) {
            Bh[n] = *(const uint2*)(bh + n * 8192);
            Bl[n] = *(const uint2*)(bl + n * 8192);
        }
        ab += 512; bh += 256; bl += 256;

#pragma unroll
        for (int n = 0; n < 8; n++) {
            mma_bf16(d[0][n], Ah0, Bh[n]);
            mma_bf16(d[1][n], Ah1, Bh[n]);
        }
#pragma unroll
        for (int n = 0; n < 8; n++) {
            mma_bf16(d[0][n], Ah0, Bl[n]);
            mma_bf16(d[1][n], Ah1, Bl[n]);
        }
#pragma unroll
        for (int n = 0; n < 8; n++) {
            mma_bf16(d[0][n], Al0, Bh[n]);
            mma_bf16(d[1][n], Al1, Bh[n]);
        }
    }

    const int g = lane >> 2, t2 = (lane & 3) * 2;
    const int tbase = tb * 128 + wx * 64 + t2;
#pragma unroll
    for (int m = 0; m < 2; m++) {
        int coA = cbk * 128 + (wy * 2 + m) * 16 + g;
        int coB = coA + 8;
        float invA = gamma[coA] / sqrtf(var[coA] + 1e-5f);
        float addA = beta[coA] - mean[coA] * invA;
        float invB = gamma[coB] / sqrtf(var[coB] + 1e-5f);
        float addB = beta[coB] - mean[coB] * invB;
        float* oA = out + ((size_t)(b * C1 + coA)) * L1 + tbase;
        float* oB = out + ((size_t)(b * C1 + coB)) * L1 + tbase;
#pragma unroll
        for (int n = 0; n < 8; n++) {
            float2 vA, vB;
            vA.x = fmaxf(d[m][n].x * invA + addA, 0.0f);
            vA.y = fmaxf(d[m][n].y * invA + addA, 0.0f);
            vB.x = fmaxf(d[m][n].z * invB + addB, 0.0f);
            vB.y = fmaxf(d[m][n].w * invB + addB, 0.0f);
            *(float2*)(oA + n * 8) = vA;
            *(float2*)(oB + n * 8) = vB;
        }
    }
}

// ---------------- conv2: warp-MMA implicit GEMM + BN + ReLU -----------------
// grid (4 t-blocks, 64 b), 8 warps, each warp: m 2 atoms (32 co) x n 8 atoms.
// Stored B atom s = out-atom + 2*kk (DIL=16 = 2 atoms).
__global__ __launch_bounds__(256, 2) void conv2_mma_kernel(
    const float* __restrict__ gamma, const float* __restrict__ beta,
    const float* __restrict__ mean,  const float* __restrict__ var,
    float* __restrict__ out)
{
    const int tid = threadIdx.x, lane = tid & 31, wx = tid >> 5;
    const int tb = blockIdx.x, b = blockIdx.y;
    const int ta0 = tb * 64 + wx * 8;

    const char* ab = (const char*)g_wf2 + (size_t)lane * 16;
    const char* bbase = (const char*)g_bf2 + ((size_t)b * 260 * 16) * 32 * 8 + (size_t)lane * 8;

    float4 d[2][8];
#pragma unroll
    for (int m = 0; m < 2; m++)
#pragma unroll
        for (int n = 0; n < 8; n++) d[m][n] = make_float4(0.f, 0.f, 0.f, 0.f);

#pragma unroll 1
    for (int c = 0; c < 48; c++) {
        int kk = c >> 4, cic = c & 15;
        uint4 Ah0 = *(const uint4*)(ab + (size_t)c * 512);
        uint4 Ah1 = *(const uint4*)(ab + (size_t)(48 + c) * 512);
        uint4 Al0 = *(const uint4*)(ab + 49152 + (size_t)c * 512);
        uint4 Al1 = *(const uint4*)(ab + 49152 + (size_t)(48 + c) * 512);
        const char* bp = bbase + (((size_t)(ta0 + 2 * kk) * 16 + cic)) * 256;
        uint2 Bh[8], Bl[8];
#pragma unroll
        for (int n = 0; n < 8; n++) {
            Bh[n] = *(const uint2*)(bp + n * 4096);
            Bl[n] = *(const uint2*)(bp + BF2_T * 8 + n * 4096);
        }
#pragma unroll
        for (int n = 0; n < 8; n++) {
            mma_bf16(d[0][n], Ah0, Bh[n]);
            mma_bf16(d[1][n], Ah1, Bh[n]);
        }
#pragma unroll
        for (int n = 0; n < 8; n++) {
            mma_bf16(d[0][n], Ah0, Bl[n]);
            mma_bf16(d[1][n], Ah1, Bl[n]);
        }
#pragma unroll
        for (int n = 0; n < 8; n++) {
            mma_bf16(d[0][n], Al0, Bh[n]);
            mma_bf16(d[1][n], Al1, Bh[n]);
        }
    }

    const int g = lane >> 2, t2 = (lane & 3) * 2;
    const int tbase = tb * 512 + wx * 64 + t2;
#pragma unroll
    for (int m = 0; m < 2; m++) {
        int coA = m * 16 + g;
        int coB = coA + 8;
        float invA = gamma[coA] / sqrtf(var[coA] + 1e-5f);
        float addA = beta[coA] - mean[coA] * invA;
        float invB = gamma[coB] / sqrtf(var[coB] + 1e-5f);
        float addB = beta[coB] - mean[coB] * invB;
        float* oA = out + ((size_t)(b * C2 + coA)) * L1U + tbase;
        float* oB = out + ((size_t)(b * C2 + coB)) * L1U + tbase;
#pragma unroll
        for (int n = 0; n < 8; n++) {
            float2 vA, vB;
            vA.x = fmaxf(d[m][n].x * invA + addA, 0.0f);
            vA.y = fmaxf(d[m][n].y * invA + addA, 0.0f);
            vB.x = fmaxf(d[m][n].z * invB + addB, 0.0f);
            vB.y = fmaxf(d[m][n].w * invB + addB, 0.0f);
            *(float2*)(oA + n * 8) = vA;
            *(float2*)(oB + n * 8) = vB;
        }
    }
}

// ---------------- linear 2x upsample ---------------------------------------
__global__ void upsample_kernel(const float* __restrict__ in,
                                float* __restrict__ out, int NC, int Lin)
{
    int idx = blockIdx.x * blockDim.x + threadIdx.x;
    int Lo = 2 * Lin;
    if (idx >= NC * Lo) return;
    int t = idx % Lo;
    int c = idx / Lo;
    const float* p = in + (size_t)c * Lin;
    int m = t >> 1;
    float v;
    if ((t & 1) == 0) {
        v = (m == 0) ? p[0] : fmaf(0.25f, p[m - 1], 0.75f * p[m]);
    } else {
        int m1 = (m + 1 < Lin) ? m + 1 : Lin - 1;
        v = fmaf(0.75f, p[m], 0.25f * p[m1]);
    }
    out[idx] = v;
}

// ---------------- final conv (32->3, dil=32) + bias ------------------------
__global__ __launch_bounds__(256) void conv_out_kernel(
    const float* __restrict__ x, const float* __restrict__ w,
    const float* __restrict__ bias, float* __restrict__ out)
{
    constexpr int CI = C2, L = L2U, DIL = 32, T_T = 256, XW = T_T + 2 * DIL;
    __shared__ float xs[CI][XW];
    __shared__ float ws[3][CI * 3];
    const int bs = blockIdx.y;
    const int t0 = blockIdx.x * T_T;
    const int tid = threadIdx.x;
    const float* xb = x + (size_t)bs * CI * L;

    for (int i = tid; i < CI * XW; i += 256) {
        int r = i / XW, c = i % XW;
        int g = t0 - DIL + c;
        g = (g < 0) ? -g : ((g >= L) ? 2 * L - 2 - g : g);
        xs[r][c] = xb[(size_t)r * L + g];
    }
    for (int i = tid; i < 3 * CI * 3; i += 256)
        ws[i / (CI * 3)][i % (CI * 3)] = w[i];
    __syncthreads();

    float a0 = bias[0], a1 = bias[1], a2 = bias[2];
    const int t = tid;
#pragma unroll
    for (int ci = 0; ci < CI; ci++) {
        float x0 = xs[ci][t], x1 = xs[ci][t + DIL], x2 = xs[ci][t + 2 * DIL];
        a0 = fmaf(ws[0][ci * 3 + 0], x0, a0); a0 = fmaf(ws[0][ci * 3 + 1], x1, a0); a0 = fmaf(ws[0][ci * 3 + 2], x2, a0);
        a1 = fmaf(ws[1][ci * 3 + 0], x0, a1); a1 = fmaf(ws[1][ci * 3 + 1], x1, a1); a1 = fmaf(ws[1][ci * 3 + 2], x2, a1);
        a2 = fmaf(ws[2][ci * 3 + 0], x0, a2); a2 = fmaf(ws[2][ci * 3 + 1], x1, a2); a2 = fmaf(ws[2][ci * 3 + 2], x2, a2);
    }
    float* op = out + (size_t)bs * 3 * L + t0 + t;
    op[0]     = a0;
    op[L]     = a1;
    op[2 * L] = a2;
}

// ---------------- valid mask ------------------------------------------------
__global__ void valid_kernel(const float* __restrict__ targets)
{
    const int bs = blockIdx.x, b = bs >> 2, s = bs & 3;
    __shared__ int any_nz;
    if (threadIdx.x == 0) any_nz = 0;
    __syncthreads();
    int local = 0;
    for (int i = threadIdx.x; i < 3 * TOUT; i += blockDim.x) {
        int c = i / TOUT, t = i % TOUT;
        if (targets[((size_t)(b * 3 + c) * TOUT + t) * 4 + s] != 0.0f) { local = 1; break; }
    }
    if (local) atomicOr(&any_nz, 1);
    __syncthreads();
    if (threadIdx.x == 0 && any_nz) atomicAdd(&g_valid, 1);
}

// ---------------- transpose-write + masked CE ------------------------------
__global__ __launch_bounds__(256) void loss_kernel(
    const float* __restrict__ targets, float* __restrict__ dout)
{
    const int bs = blockIdx.y, b = bs >> 2, s = bs & 3;
    const int t  = blockIdx.x * 256 + threadIdx.x;
    const float* y = g_buf5 + (size_t)bs * 3 * TOUT;
    float y0 = y[t], y1 = y[TOUT + t], y2 = y[2 * TOUT + t];

    size_t o0 = ((size_t)(b * 3) * TOUT + t) * 4 + s;
    const size_t cs = (size_t)TOUT * 4;
    dout[o0]          = y0;
    dout[o0 + cs]     = y1;
    dout[o0 + 2 * cs] = y2;

    float m   = fmaxf(y0, fmaxf(y1, y2));
    float lse = m + logf(expf(y0 - m) + expf(y1 - m) + expf(y2 - m));
    float t0v = targets[o0], t1v = targets[o0 + cs], t2v = targets[o0 + 2 * cs];
    float part = t0v * (lse - y0) + t1v * (lse - y1) + t2v * (lse - y2);

    __shared__ float red[256];
    red[threadIdx.x] = part;
    __syncthreads();
#pragma unroll
    for (int o = 128; o > 0; o >>= 1) {
        if (threadIdx.x < o) red[threadIdx.x] += red[threadIdx.x + o];
        __syncthreads();
    }
    if (threadIdx.x == 0) atomicAdd(&g_loss_acc, (double)red[0]);
}

__global__ void finalize_kernel(float* __restrict__ dout)
{
    dout[(size_t)BT * 3 * TOUT * ST] =
        (float)(g_loss_acc / ((double)g_valid * (double)TOUT));
}

// ---------------------------------------------------------------------------
extern "C" void kernel_launch(void* const* d_in, const int* in_sizes, int n_in,
                              void* d_out, int out_size)
{
    const float* fusion  = (const float*)d_in[0];
    const float* targets = (const float*)d_in[1];
    const float* w1      = (const float*)d_in[2];
    const float* g1 = (const float*)d_in[3];
    const float* b1 = (const float*)d_in[4];
    const float* m1 = (const float*)d_in[5];
    const float* v1 = (const float*)d_in[6];
    const float* w2      = (const float*)d_in[7];
    const float* g2 = (const float*)d_in[8];
    const float* b2 = (const float*)d_in[9];
    const float* m2 = (const float*)d_in[10];
    const float* v2 = (const float*)d_in[11];
    const float* w_out   = (const float*)d_in[12];
    const float* b_out   = (const float*)d_in[13];
    float* out = (float*)d_out;

    float *p1, *p3, *p4, *p5;
    cudaGetSymbolAddress((void**)&p1, g_buf1);
    cudaGetSymbolAddress((void**)&p3, g_buf3);
    cudaGetSymbolAddress((void**)&p4, g_buf4);
    cudaGetSymbolAddress((void**)&p5, g_buf5);

    static int smem_set = 0;
    if (!smem_set) {
        cudaFuncSetAttribute(prep_x_kernel,
                             cudaFuncAttributeMaxDynamicSharedMemorySize, 69632);
        cudaFuncSetAttribute(prep_x2_kernel,
                             cudaFuncAttributeMaxDynamicSharedMemorySize, 69632);
        smem_set = 1;
    }

    init_kernel<<<1, 1>>>();
    prep_w_kernel<<<192, 256>>>(w1);
    prep_w2_kernel<<<12, 256>>>(w2);
    prep_x_kernel<<<dim3(32, NB), 256, 69632>>>(fusion);

    conv1_mma_kernel<<<dim3(L1 / 128, C1 / 128, NB), 256>>>(g1, b1, m1, v1, p1);

    // fused upsample1 + conv2-B-fragment pack
    prep_x2_kernel<<<dim3(16, NB), 256, 69632>>>();

    conv2_mma_kernel<<<dim3(4, NB), 256>>>(g2, b2, m2, v2, p3);

    {   // upsample2
        int nc = NB * C2, total = nc * L2U;
        upsample_kernel<<<(total + 255) / 256, 256>>>(p3, p4, nc, L1U);
    }

    conv_out_kernel<<<dim3(L2U / 256, NB), 256>>>(p4, w_out, b_out, p5);

    valid_kernel<<<NB, 256>>>(targets);
    loss_kernel<<<dim3(TOUT / 256, NB), 256>>>(targets, out);
    finalize_kernel<<<1, 1>>>(out);
}

// round 16
// speedup vs baseline: 5.5865x; 1.1211x over previous
#include <cuda_runtime.h>
#include <cuda_bf16.h>
#include <math.h>

#define BT 16
#define ST 4
#define NB 64
#define NBH 32                 // half batch for the 2-stream pipeline
#define CH 512
#define C1 256
#define C2 32
#define L1 1024
#define L1U 2048
#define L2U 4096
#define TOUT 4096

// ---------------- fragment-packed GEMM operands -----------------------------
// conv1 A: g_wf[term(2)][ma(16)][chunk(96)][lane(32)] uint4 (hi term, lo term)
// conv1 B: g_bf[b][ta(130)][cic(32)][lane(32)] uint4 = (hi.x, hi.y, lo.x, lo.y)
#define WF_ELEMS (2*16*96*32)
__device__ uint4 g_wf[WF_ELEMS];
__device__ uint4 g_bf[(size_t)NB*130*32*32];

// conv2 A: g_wf2[term(2)][ma(2)][chunk(48)][lane(32)] uint4
// conv2 B: g_bf2[b][s(260)][cic(16)][lane(32)] uint4   (s = out-atom + 2kk)
#define WF2_ELEMS (2*2*48*32)
__device__ uint4 g_wf2[WF2_ELEMS];
__device__ uint4 g_bf2[(size_t)NB*260*16*32];

__device__ float g_buf1[NB*C1*L1];
__device__ float g_buf3[NB*C2*L1U];
__device__ float g_buf4[NB*C2*L2U];
__device__ float g_buf5[NB*3*TOUT];
__device__ double g_loss_acc;
__device__ int    g_valid;

#define SM_PREP (16*1028*4)    // 65792 B

__global__ void init_kernel() { g_loss_acc = 0.0; g_valid = 0; }

// ---------------- helpers ---------------------------------------------------
__device__ __forceinline__ unsigned pack_bf2(float a, float b) {
    return ((unsigned)__bfloat16_as_ushort(__float2bfloat16(b)) << 16) |
           (unsigned)__bfloat16_as_ushort(__float2bfloat16(a));
}
__device__ __forceinline__ float bf_hi(float v) {
    return __bfloat162float(__float2bfloat16(v));
}
__device__ __forceinline__ void mma_bf16(float4& d, const uint4& a, unsigned bx, unsigned by) {
    asm("mma.sync.aligned.m16n8k16.row.col.f32.bf16.bf16.f32 "
        "{%0,%1,%2,%3},{%4,%5,%6,%7},{%8,%9},{%0,%1,%2,%3};"
        : "+f"(d.x), "+f"(d.y), "+f"(d.z), "+f"(d.w)
        : "r"(a.x), "r"(a.y), "r"(a.z), "r"(a.w), "r"(bx), "r"(by));
}

// ---------------- prep: conv1 weights -> A fragments ------------------------
__global__ void prep_w_kernel(const float* __restrict__ w1)
{
    int p = blockIdx.x * 256 + threadIdx.x;
    int lane = p & 31;
    int chunk = (p >> 5) % 96;
    int ma    = (p >> 5) / 96;
    int kk  = chunk >> 5;
    int ci0 = (chunk & 31) * 16;
    int g   = lane >> 2;
    int t2  = (lane & 3) * 2;
    int coA = ma * 16 + g, coB = coA + 8;
    int k0  = ci0 + t2;

    float wA0 = w1[((size_t)coA * CH + k0)     * 3 + kk];
    float wA1 = w1[((size_t)coA * CH + k0 + 1) * 3 + kk];
    float wA8 = w1[((size_t)coA * CH + k0 + 8) * 3 + kk];
    float wA9 = w1[((size_t)coA * CH + k0 + 9) * 3 + kk];
    float wB0 = w1[((size_t)coB * CH + k0)     * 3 + kk];
    float wB1 = w1[((size_t)coB * CH + k0 + 1) * 3 + kk];
    float wB8 = w1[((size_t)coB * CH + k0 + 8) * 3 + kk];
    float wB9 = w1[((size_t)coB * CH + k0 + 9) * 3 + kk];

    uint4 hi, lo;
    hi.x = pack_bf2(wA0, wA1); hi.y = pack_bf2(wB0, wB1);
    hi.z = pack_bf2(wA8, wA9); hi.w = pack_bf2(wB8, wB9);
    lo.x = pack_bf2(wA0 - bf_hi(wA0), wA1 - bf_hi(wA1));
    lo.y = pack_bf2(wB0 - bf_hi(wB0), wB1 - bf_hi(wB1));
    lo.z = pack_bf2(wA8 - bf_hi(wA8), wA9 - bf_hi(wA9));
    lo.w = pack_bf2(wB8 - bf_hi(wB8), wB9 - bf_hi(wB9));

    size_t idx = ((size_t)ma * 96 + chunk) * 32 + lane;
    g_wf[idx] = hi;
    g_wf[(size_t)16 * 96 * 32 + idx] = lo;
}

// ---------------- prep: conv2 weights -> A fragments ------------------------
__global__ void prep_w2_kernel(const float* __restrict__ w2)
{
    int p = blockIdx.x * 256 + threadIdx.x;          // 3072 = 2*48*32
    int lane = p & 31;
    int chunk = (p >> 5) % 48;
    int ma    = (p >> 5) / 48;
    int kk  = chunk / 16;
    int ci0 = (chunk % 16) * 16;
    int g   = lane >> 2;
    int t2  = (lane & 3) * 2;
    int coA = ma * 16 + g, coB = coA + 8;
    int k0  = ci0 + t2;

    float wA0 = w2[((size_t)coA * C1 + k0)     * 3 + kk];
    float wA1 = w2[((size_t)coA * C1 + k0 + 1) * 3 + kk];
    float wA8 = w2[((size_t)coA * C1 + k0 + 8) * 3 + kk];
    float wA9 = w2[((size_t)coA * C1 + k0 + 9) * 3 + kk];
    float wB0 = w2[((size_t)coB * C1 + k0)     * 3 + kk];
    float wB1 = w2[((size_t)coB * C1 + k0 + 1) * 3 + kk];
    float wB8 = w2[((size_t)coB * C1 + k0 + 8) * 3 + kk];
    float wB9 = w2[((size_t)coB * C1 + k0 + 9) * 3 + kk];

    uint4 hi, lo;
    hi.x = pack_bf2(wA0, wA1); hi.y = pack_bf2(wB0, wB1);
    hi.z = pack_bf2(wA8, wA9); hi.w = pack_bf2(wB8, wB9);
    lo.x = pack_bf2(wA0 - bf_hi(wA0), wA1 - bf_hi(wA1));
    lo.y = pack_bf2(wB0 - bf_hi(wB0), wB1 - bf_hi(wB1));
    lo.z = pack_bf2(wA8 - bf_hi(wA8), wA9 - bf_hi(wA9));
    lo.w = pack_bf2(wB8 - bf_hi(wB8), wB9 - bf_hi(wB9));

    size_t idx = ((size_t)ma * 48 + chunk) * 32 + lane;
    g_wf2[idx] = hi;
    g_wf2[(size_t)2 * 48 * 32 + idx] = lo;
}

// ---------------- prep: x -> conv1 B fragments (vectorized, uint4) ----------
// smem ci-major [16][1028]: float4 loads AND float4 stores; fragment reads
// are conflict-free (bank = 4*t2 + g + const, all 32 distinct).
__global__ __launch_bounds__(256) void prep_x_kernel(const float* __restrict__ fusion,
                                                     int b0)
{
    extern __shared__ float st[];
    const int cic = blockIdx.x, b = blockIdx.y + b0;
    const float* fb = fusion + ((size_t)b * CH + cic * 16) * L1;

    for (int i = threadIdx.x; i < 16 * 256; i += 256) {
        int ci = i >> 8, t4 = (i & 255) * 4;
        *(float4*)&st[ci * 1028 + t4] = *(const float4*)(fb + (size_t)ci * L1 + t4);
    }
    __syncthreads();

    const int lane = threadIdx.x & 31, wid = threadIdx.x >> 5;
    const int g = lane >> 2, t2 = (lane & 3) * 2;
    for (int ta = wid; ta < 130; ta += 8) {
        int ts = ta * 8 + g - 8;
        ts = (ts < 0) ? -ts : ((ts >= L1) ? 2 * L1 - 2 - ts : ts);
        float v0 = st[(t2    ) * 1028 + ts];
        float v1 = st[(t2 + 1) * 1028 + ts];
        float v2 = st[(t2 + 8) * 1028 + ts];
        float v3 = st[(t2 + 9) * 1028 + ts];
        uint4 o;
        o.x = pack_bf2(v0, v1);
        o.y = pack_bf2(v2, v3);
        o.z = pack_bf2(v0 - bf_hi(v0), v1 - bf_hi(v1));
        o.w = pack_bf2(v2 - bf_hi(v2), v3 - bf_hi(v3));
        g_bf[(((size_t)b * 130 + ta) * 32 + cic) * 32 + lane] = o;
    }
}

// ---------------- prep: conv1-out -> upsample2x -> conv2 B fragments --------
__global__ __launch_bounds__(256) void prep_x2_kernel(int b0)
{
    extern __shared__ float st[];                    // [16][1028], ci-major
    const int cic = blockIdx.x, b = blockIdx.y + b0;
    const float* fb = g_buf1 + ((size_t)b * C1 + cic * 16) * L1;

    for (int i = threadIdx.x; i < 16 * 256; i += 256) {
        int ci = i >> 8, t4 = (i & 255) * 4;
        *(float4*)&st[ci * 1028 + t4] = *(const float4*)(fb + (size_t)ci * L1 + t4);
    }
    __syncthreads();

    const int lane = threadIdx.x & 31, wid = threadIdx.x >> 5;
    const int g = lane >> 2, t2 = (lane & 3) * 2;
    for (int s = wid; s < 260; s += 8) {
        int tp = s * 8 + g - 16;
        tp = (tp < 0) ? -tp : ((tp >= L1U) ? 2 * L1U - 2 - tp : tp);
        int m = tp >> 1;
        float wlo, whi;  int mlo, mhi;
        if ((tp & 1) == 0) {
            if (m == 0) { mlo = 0; mhi = 0; wlo = 1.0f; whi = 0.0f; }
            else { mlo = m - 1; mhi = m; wlo = 0.25f; whi = 0.75f; }
        } else {
            mlo = m; mhi = (m + 1 < L1) ? m + 1 : L1 - 1; wlo = 0.75f; whi = 0.25f;
        }
        float v0 = wlo * st[(t2    ) * 1028 + mlo] + whi * st[(t2    ) * 1028 + mhi];
        float v1 = wlo * st[(t2 + 1) * 1028 + mlo] + whi * st[(t2 + 1) * 1028 + mhi];
        float v2 = wlo * st[(t2 + 8) * 1028 + mlo] + whi * st[(t2 + 8) * 1028 + mhi];
        float v3 = wlo * st[(t2 + 9) * 1028 + mlo] + whi * st[(t2 + 9) * 1028 + mhi];
        uint4 o;
        o.x = pack_bf2(v0, v1);
        o.y = pack_bf2(v2, v3);
        o.z = pack_bf2(v0 - bf_hi(v0), v1 - bf_hi(v1));
        o.w = pack_bf2(v2 - bf_hi(v2), v3 - bf_hi(v3));
        g_bf2[(((size_t)b * 260 + s) * 16 + cic) * 32 + lane] = o;
    }
}

// ---------------- conv1: warp-MMA implicit GEMM + BN + ReLU -----------------
__global__ __launch_bounds__(256, 2) void conv1_mma_kernel(
    const float* __restrict__ gamma, const float* __restrict__ beta,
    const float* __restrict__ mean,  const float* __restrict__ var,
    float* __restrict__ out, int b0)
{
    const int tid = threadIdx.x, lane = tid & 31, wid = tid >> 5;
    const int wy = wid & 3, wx = wid >> 2;
    const int tb = blockIdx.x, cbk = blockIdx.y, b = blockIdx.z + b0;
    const int ma0 = cbk * 8 + wy * 2;
    const int ta0 = tb * 16 + wx * 8;

    const char* ab = (const char*)g_wf + (size_t)ma0 * 49152 + (size_t)lane * 16;
    const char* bq = (const char*)g_bf + (((size_t)b * 130 + ta0) * 32) * 512 + (size_t)lane * 16;

    float4 d[2][8];
#pragma unroll
    for (int m = 0; m < 2; m++)
#pragma unroll
        for (int n = 0; n < 8; n++) d[m][n] = make_float4(0.f, 0.f, 0.f, 0.f);

#pragma unroll 1
    for (int c = 0; c < 96; c++) {
        uint4 Ah0 = *(const uint4*)(ab);
        uint4 Ah1 = *(const uint4*)(ab + 49152);
        uint4 Al0 = *(const uint4*)(ab + 786432);
        uint4 Al1 = *(const uint4*)(ab + 786432 + 49152);
        uint4 Bq[8];
#pragma unroll
        for (int n = 0; n < 8; n++) Bq[n] = *(const uint4*)(bq + n * 16384);
        ab += 512; bq += 512;

#pragma unroll
        for (int n = 0; n < 8; n++) {
            mma_bf16(d[0][n], Ah0, Bq[n].x, Bq[n].y);
            mma_bf16(d[1][n], Ah1, Bq[n].x, Bq[n].y);
        }
#pragma unroll
        for (int n = 0; n < 8; n++) {
            mma_bf16(d[0][n], Ah0, Bq[n].z, Bq[n].w);
            mma_bf16(d[1][n], Ah1, Bq[n].z, Bq[n].w);
        }
#pragma unroll
        for (int n = 0; n < 8; n++) {
            mma_bf16(d[0][n], Al0, Bq[n].x, Bq[n].y);
            mma_bf16(d[1][n], Al1, Bq[n].x, Bq[n].y);
        }
    }

    const int g = lane >> 2, t2 = (lane & 3) * 2;
    const int tbase = tb * 128 + wx * 64 + t2;
#pragma unroll
    for (int m = 0; m < 2; m++) {
        int coA = cbk * 128 + (wy * 2 + m) * 16 + g;
        int coB = coA + 8;
        float invA = gamma[coA] / sqrtf(var[coA] + 1e-5f);
        float addA = beta[coA] - mean[coA] * invA;
        float invB = gamma[coB] / sqrtf(var[coB] + 1e-5f);
        float addB = beta[coB] - mean[coB] * invB;
        float* oA = out + ((size_t)(b * C1 + coA)) * L1 + tbase;
        float* oB = out + ((size_t)(b * C1 + coB)) * L1 + tbase;
#pragma unroll
        for (int n = 0; n < 8; n++) {
            float2 vA, vB;
            vA.x = fmaxf(d[m][n].x * invA + addA, 0.0f);
            vA.y = fmaxf(d[m][n].y * invA + addA, 0.0f);
            vB.x = fmaxf(d[m][n].z * invB + addB, 0.0f);
            vB.y = fmaxf(d[m][n].w * invB + addB, 0.0f);
            *(float2*)(oA + n * 8) = vA;
            *(float2*)(oB + n * 8) = vB;
        }
    }
}

// ---------------- conv2: warp-MMA implicit GEMM + BN + ReLU -----------------
__global__ __launch_bounds__(256, 2) void conv2_mma_kernel(
    const float* __restrict__ gamma, const float* __restrict__ beta,
    const float* __restrict__ mean,  const float* __restrict__ var,
    float* __restrict__ out, int b0)
{
    const int tid = threadIdx.x, lane = tid & 31, wx = tid >> 5;
    const int tb = blockIdx.x, b = blockIdx.y + b0;
    const int ta0 = tb * 64 + wx * 8;

    const char* ab = (const char*)g_wf2 + (size_t)lane * 16;
    const char* bbase = (const char*)g_bf2 + ((size_t)b * 260 * 16 * 32) * 16 + (size_t)lane * 16;

    float4 d[2][8];
#pragma unroll
    for (int m = 0; m < 2; m++)
#pragma unroll
        for (int n = 0; n < 8; n++) d[m][n] = make_float4(0.f, 0.f, 0.f, 0.f);

#pragma unroll 1
    for (int c = 0; c < 48; c++) {
        int kk = c >> 4, cic = c & 15;
        uint4 Ah0 = *(const uint4*)(ab + (size_t)c * 512);
        uint4 Ah1 = *(const uint4*)(ab + (size_t)(48 + c) * 512);
        uint4 Al0 = *(const uint4*)(ab + 49152 + (size_t)c * 512);
        uint4 Al1 = *(const uint4*)(ab + 49152 + (size_t)(48 + c) * 512);
        const char* bp = bbase + ((size_t)(ta0 + 2 * kk) * 16 + cic) * 512;
        uint4 Bq[8];
#pragma unroll
        for (int n = 0; n < 8; n++) Bq[n] = *(const uint4*)(bp + n * 8192);

#pragma unroll
        for (int n = 0; n < 8; n++) {
            mma_bf16(d[0][n], Ah0, Bq[n].x, Bq[n].y);
            mma_bf16(d[1][n], Ah1, Bq[n].x, Bq[n].y);
        }
#pragma unroll
        for (int n = 0; n < 8; n++) {
            mma_bf16(d[0][n], Ah0, Bq[n].z, Bq[n].w);
            mma_bf16(d[1][n], Ah1, Bq[n].z, Bq[n].w);
        }
#pragma unroll
        for (int n = 0; n < 8; n++) {
            mma_bf16(d[0][n], Al0, Bq[n].x, Bq[n].y);
            mma_bf16(d[1][n], Al1, Bq[n].x, Bq[n].y);
        }
    }

    const int g = lane >> 2, t2 = (lane & 3) * 2;
    const int tbase = tb * 512 + wx * 64 + t2;
#pragma unroll
    for (int m = 0; m < 2; m++) {
        int coA = m * 16 + g;
        int coB = coA + 8;
        float invA = gamma[coA] / sqrtf(var[coA] + 1e-5f);
        float addA = beta[coA] - mean[coA] * invA;
        float invB = gamma[coB] / sqrtf(var[coB] + 1e-5f);
        float addB = beta[coB] - mean[coB] * invB;
        float* oA = out + ((size_t)(b * C2 + coA)) * L1U + tbase;
        float* oB = out + ((size_t)(b * C2 + coB)) * L1U + tbase;
#pragma unroll
        for (int n = 0; n < 8; n++) {
            float2 vA, vB;
            vA.x = fmaxf(d[m][n].x * invA + addA, 0.0f);
            vA.y = fmaxf(d[m][n].y * invA + addA, 0.0f);
            vB.x = fmaxf(d[m][n].z * invB + addB, 0.0f);
            vB.y = fmaxf(d[m][n].w * invB + addB, 0.0f);
            *(float2*)(oA + n * 8) = vA;
            *(float2*)(oB + n * 8) = vB;
        }
    }
}

// ---------------- linear 2x upsample ---------------------------------------
__global__ void upsample_kernel(const float* __restrict__ in,
                                float* __restrict__ out, int NC, int Lin)
{
    int idx = blockIdx.x * blockDim.x + threadIdx.x;
    int Lo = 2 * Lin;
    if (idx >= NC * Lo) return;
    int t = idx % Lo;
    int c = idx / Lo;
    const float* p = in + (size_t)c * Lin;
    int m = t >> 1;
    float v;
    if ((t & 1) == 0) {
        v = (m == 0) ? p[0] : fmaf(0.25f, p[m - 1], 0.75f * p[m]);
    } else {
        int m1 = (m + 1 < Lin) ? m + 1 : Lin - 1;
        v = fmaf(0.75f, p[m], 0.25f * p[m1]);
    }
    out[idx] = v;
}

// ---------------- final conv (32->3, dil=32) + bias ------------------------
__global__ __launch_bounds__(256) void conv_out_kernel(
    const float* __restrict__ x, const float* __restrict__ w,
    const float* __restrict__ bias, float* __restrict__ out)
{
    constexpr int CI = C2, L = L2U, DIL = 32, T_T = 256, XW = T_T + 2 * DIL;
    __shared__ float xs[CI][XW];
    __shared__ float ws[3][CI * 3];
    const int bs = blockIdx.y;
    const int t0 = blockIdx.x * T_T;
    const int tid = threadIdx.x;
    const float* xb = x + (size_t)bs * CI * L;

    for (int i = tid; i < CI * XW; i += 256) {
        int r = i / XW, c = i % XW;
        int g = t0 - DIL + c;
        g = (g < 0) ? -g : ((g >= L) ? 2 * L - 2 - g : g);
        xs[r][c] = xb[(size_t)r * L + g];
    }
    for (int i = tid; i < 3 * CI * 3; i += 256)
        ws[i / (CI * 3)][i % (CI * 3)] = w[i];
    __syncthreads();

    float a0 = bias[0], a1 = bias[1], a2 = bias[2];
    const int t = tid;
#pragma unroll
    for (int ci = 0; ci < CI; ci++) {
        float x0 = xs[ci][t], x1 = xs[ci][t + DIL], x2 = xs[ci][t + 2 * DIL];
        a0 = fmaf(ws[0][ci * 3 + 0], x0, a0); a0 = fmaf(ws[0][ci * 3 + 1], x1, a0); a0 = fmaf(ws[0][ci * 3 + 2], x2, a0);
        a1 = fmaf(ws[1][ci * 3 + 0], x0, a1); a1 = fmaf(ws[1][ci * 3 + 1], x1, a1); a1 = fmaf(ws[1][ci * 3 + 2], x2, a1);
        a2 = fmaf(ws[2][ci * 3 + 0], x0, a2); a2 = fmaf(ws[2][ci * 3 + 1], x1, a2); a2 = fmaf(ws[2][ci * 3 + 2], x2, a2);
    }
    float* op = out + (size_t)bs * 3 * L + t0 + t;
    op[0]     = a0;
    op[L]     = a1;
    op[2 * L] = a2;
}

// ---------------- valid mask ------------------------------------------------
__global__ void valid_kernel(const float* __restrict__ targets)
{
    const int bs = blockIdx.x, b = bs >> 2, s = bs & 3;
    __shared__ int any_nz;
    if (threadIdx.x == 0) any_nz = 0;
    __syncthreads();
    int local = 0;
    for (int i = threadIdx.x; i < 3 * TOUT; i += blockDim.x) {
        int c = i / TOUT, t = i % TOUT;
        if (targets[((size_t)(b * 3 + c) * TOUT + t) * 4 + s] != 0.0f) { local = 1; break; }
    }
    if (local) atomicOr(&any_nz, 1);
    __syncthreads();
    if (threadIdx.x == 0 && any_nz) atomicAdd(&g_valid, 1);
}

// ---------------- transpose-write + masked CE ------------------------------
__global__ __launch_bounds__(256) void loss_kernel(
    const float* __restrict__ targets, float* __restrict__ dout)
{
    const int bs = blockIdx.y, b = bs >> 2, s = bs & 3;
    const int t  = blockIdx.x * 256 + threadIdx.x;
    const float* y = g_buf5 + (size_t)bs * 3 * TOUT;
    float y0 = y[t], y1 = y[TOUT + t], y2 = y[2 * TOUT + t];

    size_t o0 = ((size_t)(b * 3) * TOUT + t) * 4 + s;
    const size_t cs = (size_t)TOUT * 4;
    dout[o0]          = y0;
    dout[o0 + cs]     = y1;
    dout[o0 + 2 * cs] = y2;

    float m   = fmaxf(y0, fmaxf(y1, y2));
    float lse = m + logf(expf(y0 - m) + expf(y1 - m) + expf(y2 - m));
    float t0v = targets[o0], t1v = targets[o0 + cs], t2v = targets[o0 + 2 * cs];
    float part = t0v * (lse - y0) + t1v * (lse - y1) + t2v * (lse - y2);

    __shared__ float red[256];
    red[threadIdx.x] = part;
    __syncthreads();
#pragma unroll
    for (int o = 128; o > 0; o >>= 1) {
        if (threadIdx.x < o) red[threadIdx.x] += red[threadIdx.x + o];
        __syncthreads();
    }
    if (threadIdx.x == 0) atomicAdd(&g_loss_acc, (double)red[0]);
}

__global__ void finalize_kernel(float* __restrict__ dout)
{
    dout[(size_t)BT * 3 * TOUT * ST] =
        (float)(g_loss_acc / ((double)g_valid * (double)TOUT));
}

// ---------------- stream/event resources (created at load, pre-baseline) ----
static cudaStream_t g_s1 = 0;
static cudaEvent_t  g_eF = 0, g_e0 = 0, g_eD0 = 0;
static bool         g_res_ok = false;
struct ResInit {
    ResInit() {
        if (cudaStreamCreateWithFlags(&g_s1, cudaStreamNonBlocking) != cudaSuccess) return;
        if (cudaEventCreateWithFlags(&g_eF,  cudaEventDisableTiming) != cudaSuccess) return;
        if (cudaEventCreateWithFlags(&g_e0,  cudaEventDisableTiming) != cudaSuccess) return;
        if (cudaEventCreateWithFlags(&g_eD0, cudaEventDisableTiming) != cudaSuccess) return;
        cudaFuncSetAttribute(prep_x_kernel,
                             cudaFuncAttributeMaxDynamicSharedMemorySize, SM_PREP);
        cudaFuncSetAttribute(prep_x2_kernel,
                             cudaFuncAttributeMaxDynamicSharedMemorySize, SM_PREP);
        g_res_ok = true;
    }
};
static ResInit g_res_init;

// ---------------------------------------------------------------------------
extern "C" void kernel_launch(void* const* d_in, const int* in_sizes, int n_in,
                              void* d_out, int out_size)
{
    const float* fusion  = (const float*)d_in[0];
    const float* targets = (const float*)d_in[1];
    const float* w1      = (const float*)d_in[2];
    const float* g1 = (const float*)d_in[3];
    const float* b1 = (const float*)d_in[4];
    const float* m1 = (const float*)d_in[5];
    const float* v1 = (const float*)d_in[6];
    const float* w2      = (const float*)d_in[7];
    const float* g2 = (const float*)d_in[8];
    const float* b2 = (const float*)d_in[9];
    const float* m2 = (const float*)d_in[10];
    const float* v2 = (const float*)d_in[11];
    const float* w_out   = (const float*)d_in[12];
    const float* b_out   = (const float*)d_in[13];
    float* out = (float*)d_out;

    float *p1, *p3, *p4, *p5;
    cudaGetSymbolAddress((void**)&p1, g_buf1);
    cudaGetSymbolAddress((void**)&p3, g_buf3);
    cudaGetSymbolAddress((void**)&p4, g_buf4);
    cudaGetSymbolAddress((void**)&p5, g_buf5);

    init_kernel<<<1, 1>>>();
    prep_w_kernel<<<192, 256>>>(w1);
    prep_w2_kernel<<<12, 256>>>(w2);

    if (g_res_ok) {
        // -------- 2-stream batch-split pipeline --------
        cudaEventRecord(g_eF, 0);
        prep_x_kernel<<<dim3(32, NBH), 256, SM_PREP>>>(fusion, 0);
        cudaEventRecord(g_e0, 0);

        // s1: H0 chain (+ valid overlapped under prep_x)
        cudaStreamWaitEvent(g_s1, g_eF, 0);
        valid_kernel<<<NB, 256, 0, g_s1>>>(targets);
        cudaStreamWaitEvent(g_s1, g_e0, 0);
        conv1_mma_kernel<<<dim3(8, 2, NBH), 256, 0, g_s1>>>(g1, b1, m1, v1, p1, 0);
        prep_x2_kernel<<<dim3(16, NBH), 256, SM_PREP, g_s1>>>(0);
        conv2_mma_kernel<<<dim3(4, NBH), 256, 0, g_s1>>>(g2, b2, m2, v2, p3, 0);
        upsample_kernel<<<(NBH * C2 * L2U + 255) / 256, 256, 0, g_s1>>>(
            p3, p4, NBH * C2, L1U);
        conv_out_kernel<<<dim3(16, NBH), 256, 0, g_s1>>>(p4, w_out, b_out, p5);
        cudaEventRecord(g_eD0, g_s1);

        // s0: H1 chain (overlaps s1's tensor work with mem work and vice versa)
        prep_x_kernel<<<dim3(32, NBH), 256, SM_PREP>>>(fusion, NBH);
        conv1_mma_kernel<<<dim3(8, 2, NBH), 256>>>(g1, b1, m1, v1, p1, NBH);
        prep_x2_kernel<<<dim3(16, NBH), 256, SM_PREP>>>(NBH);
        conv2_mma_kernel<<<dim3(4, NBH), 256>>>(g2, b2, m2, v2, p3, NBH);
        upsample_kernel<<<(NBH * C2 * L2U + 255) / 256, 256>>>(
            p3 + (size_t)NBH * C2 * L1U, p4 + (size_t)NBH * C2 * L2U, NBH * C2, L1U);
        conv_out_kernel<<<dim3(16, NBH), 256>>>(
            p4 + (size_t)NBH * C2 * L2U, w_out, b_out, p5 + (size_t)NBH * 3 * TOUT);

        cudaStreamWaitEvent(0, g_eD0, 0);
        loss_kernel<<<dim3(16, NB), 256>>>(targets, out);
        finalize_kernel<<<1, 1>>>(out);
    } else {
        // -------- fallback: single-stream serial --------
        cudaFuncSetAttribute(prep_x_kernel,
                             cudaFuncAttributeMaxDynamicSharedMemorySize, SM_PREP);
        cudaFuncSetAttribute(prep_x2_kernel,
                             cudaFuncAttributeMaxDynamicSharedMemorySize, SM_PREP);
        prep_x_kernel<<<dim3(32, NB), 256, SM_PREP>>>(fusion, 0);
        conv1_mma_kernel<<<dim3(8, 2, NB), 256>>>(g1, b1, m1, v1, p1, 0);
        prep_x2_kernel<<<dim3(16, NB), 256, SM_PREP>>>(0);
        conv2_mma_kernel<<<dim3(4, NB), 256>>>(g2, b2, m2, v2, p3, 0);
        upsample_kernel<<<(NB * C2 * L2U + 255) / 256, 256>>>(p3, p4, NB * C2, L1U);
        conv_out_kernel<<<dim3(16, NB), 256>>>(p4, w_out, b_out, p5);
        valid_kernel<<<NB, 256>>>(targets);
        loss_kernel<<<dim3(16, NB), 256>>>(targets, out);
        finalize_kernel<<<1, 1>>>(out);
    }
}